// round 4
// baseline (speedup 1.0000x reference)
#include <cuda_runtime.h>
#include <cuda_bf16.h>
#include <math.h>
#include <stdint.h>

// Problem constants
#define NUM_K  1024
#define DIM    256
#define HWSZ   1024
#define NTOK   32768
#define DECAYF 0.99f
#define OMD    0.01f
#define CCOST  0.25f
#define EPSF   1e-5f

// Output layout
#define OFF_Q    0
#define OFF_LOSS 8388608
#define OFF_PERP 8388609
#define OFF_CB   8388610
#define OFF_CS   8650754
#define OFF_EDW  8651778

// Scratch
__device__ __align__(16) float g_dw[NUM_K * DIM];
__device__ float g_cnorm[NUM_K];
__device__ int   g_counts[NUM_K];
__device__ int   g_idx[NTOK];
__device__ float g_sumsq;
__device__ float g_csadj[NUM_K];

// tf32 splits: row-major, 512 cols (0..255 = hi, 256..511 = lo)
__device__ __align__(16) float g_zsplit[NTOK  * 512];   // 64 MB
__device__ __align__(16) float g_csplit[NUM_K * 512];   // 2 MB

__device__ __forceinline__ uint32_t tf32_rna(float x) {
    uint32_t u;
    asm("cvt.rna.tf32.f32 %0, %1;" : "=r"(u) : "f"(x));
    return u;
}
__device__ __forceinline__ void split_tf32(float x, float& hi, float& lo) {
    hi = __uint_as_float(tf32_rna(x));
    lo = __uint_as_float(tf32_rna(x - hi));
}

// ---------------------------------------------------------------------------
// K1: init scratch + codebook norms + codebook tf32 split. grid=1024, block=64
// ---------------------------------------------------------------------------
__global__ void k_init(const float* __restrict__ cb) {
    const int k = blockIdx.x;
    const int t = threadIdx.x;
    ((float4*)(g_dw + k * DIM))[t] = make_float4(0.f, 0.f, 0.f, 0.f);
    const float4 c4 = ((const float4*)(cb + k * DIM))[t];
    float s = c4.x * c4.x + c4.y * c4.y + c4.z * c4.z + c4.w * c4.w;
    #pragma unroll
    for (int o = 16; o > 0; o >>= 1) s += __shfl_xor_sync(0xffffffffu, s, o);
    __shared__ float red[2];
    if ((t & 31) == 0) red[t >> 5] = s;
    #pragma unroll
    for (int j = 0; j < 4; j++) {
        const int d = t + 64 * j;
        float hi, lo;
        split_tf32(cb[k * DIM + d], hi, lo);
        g_csplit[(size_t)k * 512 + d]       = hi;
        g_csplit[(size_t)k * 512 + 256 + d] = lo;
    }
    __syncthreads();
    if (t == 0) {
        g_cnorm[k]  = red[0] + red[1];
        g_counts[k] = 0;
        if (k == 0) g_sumsq = 0.f;
    }
}

// ---------------------------------------------------------------------------
// K2: transpose + tf32-split z into token-major layout. grid=1024, block=256
// ---------------------------------------------------------------------------
__global__ __launch_bounds__(256)
void k_zsplit(const float* __restrict__ z) {
    __shared__ float s[256][33];
    const int b    = blockIdx.x >> 5;
    const int hwc  = blockIdx.x & 31;
    const int tid  = threadIdx.x;
    const int lane = tid & 31;
    const int grp  = tid >> 5;   // 0..7

    const float* zb = z + (size_t)b * DIM * HWSZ + hwc * 32;
    #pragma unroll 8
    for (int dd = 0; dd < 32; ++dd) {
        const int d = grp * 32 + dd;
        s[d][lane] = zb[(size_t)d * HWSZ + lane];
    }
    __syncthreads();

    #pragma unroll
    for (int tg = 0; tg < 4; ++tg) {
        const int tok = tg * 8 + grp;
        const size_t rowo = ((size_t)(b * HWSZ + hwc * 32 + tok)) * 512;
        #pragma unroll
        for (int j = 0; j < 8; ++j) {
            const int d = j * 32 + lane;
            float hi, lo;
            split_tf32(s[d][tok], hi, lo);
            g_zsplit[rowo + d]       = hi;
            g_zsplit[rowo + 256 + d] = lo;
        }
    }
}

// ---------------------------------------------------------------------------
// K3: 3xTF32 mma.sync distance GEMM + argmin.
// grid=256 CTAs (128 tokens), block=256 (8 warps, 4m x 2n), warp tile 32x64.
// Phases over K'=768: (A_hi,B_hi), (A_hi,B_lo), (A_lo,B_hi).
// ---------------------------------------------------------------------------
#define BM 128
#define BN 128
#define BK 16
#define SSTR 20   // smem row stride (floats), conflict-free for fragment loads

__global__ __launch_bounds__(256, 2)
void k_argmin_mma() {
    __shared__ float As[2][BM * SSTR];
    __shared__ float Bs[2][BN * SSTR];
    __shared__ float sminv[2][BM];
    __shared__ int   smini[2][BM];

    const int tid   = threadIdx.x;
    const int lane  = tid & 31;
    const int wid   = tid >> 5;
    const int warpM = wid & 3;      // 0..3
    const int warpN = wid >> 2;     // 0..1
    const int gid   = lane >> 2;    // 0..7
    const int tq    = lane & 3;     // 0..3
    const int tok0  = blockIdx.x * BM;

    float acc[2][8][4];
    float minv[4];
    int   mini[4];
    #pragma unroll
    for (int s = 0; s < 4; ++s) { minv[s] = 3.4e38f; mini[s] = 0; }
    #pragma unroll
    for (int mt = 0; mt < 2; ++mt)
        #pragma unroll
        for (int nt = 0; nt < 8; ++nt)
            #pragma unroll
            for (int c = 0; c < 4; ++c) acc[mt][nt][c] = 0.f;

    auto load_chunk = [&](int kk, int ct, int buf) {
        const int phase = kk >> 4;
        const int kc    = kk & 15;
        const int aoff  = ((phase == 2) ? 256 : 0) + kc * BK;
        const int boff  = ((phase == 1) ? 256 : 0) + kc * BK;
        #pragma unroll
        for (int i = 0; i < 2; ++i) {
            const int idx = tid * 2 + i;
            const int row = idx >> 2;
            const int cq  = idx & 3;
            const float4 av = *(const float4*)(g_zsplit + ((size_t)(tok0 + row)) * 512 + aoff + cq * 4);
            *(float4*)&As[buf][row * SSTR + cq * 4] = av;
            const float4 bv = *(const float4*)(g_csplit + ((size_t)(ct * BN + row)) * 512 + boff + cq * 4);
            *(float4*)&Bs[buf][row * SSTR + cq * 4] = bv;
        }
    };

    for (int ct = 0; ct < 8; ++ct) {
        load_chunk(0, ct, 0);
        __syncthreads();

        for (int kk = 0; kk < 48; ++kk) {
            const int buf = kk & 1;
            if (kk + 1 < 48) load_chunk(kk + 1, ct, buf ^ 1);

            const float* as = As[buf];
            const float* bs = Bs[buf];
            #pragma unroll
            for (int ks = 0; ks < 2; ++ks) {
                const int k0 = ks * 8 + tq;
                uint32_t a[2][4];
                #pragma unroll
                for (int mt = 0; mt < 2; ++mt) {
                    const int base = (warpM * 32 + mt * 16 + gid) * SSTR + k0;
                    a[mt][0] = __float_as_uint(as[base]);
                    a[mt][1] = __float_as_uint(as[base + 8 * SSTR]);
                    a[mt][2] = __float_as_uint(as[base + 4]);
                    a[mt][3] = __float_as_uint(as[base + 8 * SSTR + 4]);
                }
                #pragma unroll
                for (int nt = 0; nt < 8; ++nt) {
                    const int bbase = (warpN * 64 + nt * 8 + gid) * SSTR + k0;
                    const uint32_t b0 = __float_as_uint(bs[bbase]);
                    const uint32_t b1 = __float_as_uint(bs[bbase + 4]);
                    #pragma unroll
                    for (int mt = 0; mt < 2; ++mt) {
                        asm volatile(
                            "mma.sync.aligned.m16n8k8.row.col.f32.tf32.tf32.f32 "
                            "{%0,%1,%2,%3}, {%4,%5,%6,%7}, {%8,%9}, {%0,%1,%2,%3};"
                            : "+f"(acc[mt][nt][0]), "+f"(acc[mt][nt][1]),
                              "+f"(acc[mt][nt][2]), "+f"(acc[mt][nt][3])
                            : "r"(a[mt][0]), "r"(a[mt][1]), "r"(a[mt][2]), "r"(a[mt][3]),
                              "r"(b0), "r"(b1));
                    }
                }
            }
            __syncthreads();
        }

        // fold this code tile into the running argmin (ascending n, strict <)
        #pragma unroll
        for (int mt = 0; mt < 2; ++mt) {
            #pragma unroll
            for (int nt = 0; nt < 8; ++nt) {
                const int n0 = ct * BN + warpN * 64 + nt * 8 + tq * 2;
                const float cn0 = __ldg(&g_cnorm[n0]);
                const float cn1 = __ldg(&g_cnorm[n0 + 1]);
                const float s00 = fmaf(-2.f, acc[mt][nt][0], cn0);
                const float s01 = fmaf(-2.f, acc[mt][nt][1], cn1);
                const float s10 = fmaf(-2.f, acc[mt][nt][2], cn0);
                const float s11 = fmaf(-2.f, acc[mt][nt][3], cn1);
                const int s0 = mt * 2, s1 = mt * 2 + 1;
                if (s00 < minv[s0]) { minv[s0] = s00; mini[s0] = n0; }
                if (s01 < minv[s0]) { minv[s0] = s01; mini[s0] = n0 + 1; }
                if (s10 < minv[s1]) { minv[s1] = s10; mini[s1] = n0; }
                if (s11 < minv[s1]) { minv[s1] = s11; mini[s1] = n0 + 1; }
                acc[mt][nt][0] = acc[mt][nt][1] = acc[mt][nt][2] = acc[mt][nt][3] = 0.f;
            }
        }
    }

    // reduce across the 4 lanes sharing each row (tq dimension)
    #pragma unroll
    for (int s = 0; s < 4; ++s) {
        float v  = minv[s];
        int   ix = mini[s];
        #pragma unroll
        for (int off = 1; off <= 2; off <<= 1) {
            const float ov = __shfl_xor_sync(0xffffffffu, v, off);
            const int   oi = __shfl_xor_sync(0xffffffffu, ix, off);
            if (ov < v || (ov == v && oi < ix)) { v = ov; ix = oi; }
        }
        if (tq == 0) {
            const int row = warpM * 32 + (s >> 1) * 16 + (s & 1) * 8 + gid;
            sminv[warpN][row] = v;
            smini[warpN][row] = ix;
        }
    }
    __syncthreads();

    // combine the two warpN halves (each saw a disjoint half of every code tile)
    if (tid < BM) {
        float v0 = sminv[0][tid];
        int   i0 = smini[0][tid];
        const float v1 = sminv[1][tid];
        const int   i1 = smini[1][tid];
        if (v1 < v0 || (v1 == v0 && i1 < i0)) { v0 = v1; i0 = i1; }
        g_idx[tok0 + tid] = i0;
        atomicAdd(&g_counts[i0], 1);
    }
}

// ---------------------------------------------------------------------------
// K4: quantized output + dw scatter + loss partial. grid=1024, block=256
// ---------------------------------------------------------------------------
__global__ __launch_bounds__(256)
void k_scatter(const float* __restrict__ z, const float* __restrict__ cb,
               float* __restrict__ out) {
    const int tid  = threadIdx.x;
    const int lane = tid & 31;
    const int w    = tid >> 5;
    const int tok0 = blockIdx.x * 32;
    const int b    = tok0 >> 10;
    const int hw   = (tok0 & 1023) + lane;
    const int tok  = tok0 + lane;
    const int k    = g_idx[tok];

    const float* zrow  = z  + (size_t)b * DIM * HWSZ + hw;
    float*       qrow  = out + OFF_Q + (size_t)b * DIM * HWSZ + hw;
    const float* crow  = cb + (size_t)k * DIM;
    float*       dwrow = g_dw + (size_t)k * DIM;

    float acc = 0.f;
    #pragma unroll 4
    for (int dd = 0; dd < 32; ++dd) {
        const int d = w + dd * 8;
        const float zv = zrow[(size_t)d * HWSZ];
        const float cv = crow[d];
        qrow[(size_t)d * HWSZ] = zv + (cv - zv);
        const float df = zv - cv;
        acc = fmaf(df, df, acc);
        atomicAdd(&dwrow[d], zv);
    }
    #pragma unroll
    for (int o = 16; o > 0; o >>= 1) acc += __shfl_xor_sync(0xffffffffu, acc, o);
    if (lane == 0) atomicAdd(&g_sumsq, acc);
}

// ---------------------------------------------------------------------------
// K5: cluster-size EMA, n-sum, perplexity, loss. 1 block, 1024 threads
// ---------------------------------------------------------------------------
__global__ void k_finalize1(const float* __restrict__ ema_cs, float* __restrict__ out) {
    __shared__ float red[32];
    __shared__ float nsh;
    const int k = threadIdx.x;

    const float cnt = (float)g_counts[k];
    const float ncs = ema_cs[k] * DECAYF + OMD * cnt;
    out[OFF_CS + k] = ncs;

    float s = ncs;
    #pragma unroll
    for (int o = 16; o > 0; o >>= 1) s += __shfl_xor_sync(0xffffffffu, s, o);
    if ((k & 31) == 0) red[k >> 5] = s;
    __syncthreads();
    if (k < 32) {
        float t = red[k];
        #pragma unroll
        for (int o = 16; o > 0; o >>= 1) t += __shfl_xor_sync(0xffffffffu, t, o);
        if (k == 0) nsh = t;
    }
    __syncthreads();
    const float n = nsh;
    g_csadj[k] = (ncs + EPSF) / (n + NUM_K * EPSF) * n;

    const float p = cnt / (float)NTOK;
    float s2 = p * logf(p + 1e-10f);
    #pragma unroll
    for (int o = 16; o > 0; o >>= 1) s2 += __shfl_xor_sync(0xffffffffu, s2, o);
    if ((k & 31) == 0) red[k >> 5] = s2;
    __syncthreads();
    if (k == 0) {
        float t = 0.f;
        #pragma unroll
        for (int i = 0; i < 32; i++) t += red[i];
        out[OFF_PERP] = expf(-t);
        out[OFF_LOSS] = CCOST * g_sumsq / (float)(NTOK * DIM);
    }
}

// ---------------------------------------------------------------------------
// K6: ema_dw EMA + codebook division. grid=1024, block=256
// ---------------------------------------------------------------------------
__global__ void k_finalize2(const float* __restrict__ ema_dw, float* __restrict__ out) {
    const int k = blockIdx.x;
    const int d = threadIdx.x;
    const size_t o = (size_t)k * DIM + d;
    const float nd = ema_dw[o] * DECAYF + OMD * g_dw[o];
    out[OFF_EDW + o] = nd;
    out[OFF_CB  + o] = nd / g_csadj[k];
}

// ---------------------------------------------------------------------------
extern "C" void kernel_launch(void* const* d_in, const int* in_sizes, int n_in,
                              void* d_out, int out_size) {
    const float* z      = (const float*)d_in[0];
    const float* cb     = (const float*)d_in[1];
    const float* ema_cs = (const float*)d_in[2];
    const float* ema_dw = (const float*)d_in[3];
    float* out = (float*)d_out;

    k_init<<<NUM_K, 64>>>(cb);
    k_zsplit<<<1024, 256>>>(z);
    k_argmin_mma<<<NTOK / BM, 256>>>();
    k_scatter<<<NTOK / 32, 256>>>(z, cb, out);
    k_finalize1<<<1, 1024>>>(ema_cs, out);
    k_finalize2<<<NUM_K, DIM>>>(ema_dw, out);
}

// round 5
// speedup vs baseline: 1.2032x; 1.2032x over previous
#include <cuda_runtime.h>
#include <cuda_bf16.h>
#include <math.h>
#include <stdint.h>

// Problem constants
#define NUM_K  1024
#define DIM    256
#define HWSZ   1024
#define NTOK   32768
#define DECAYF 0.99f
#define OMD    0.01f
#define CCOST  0.25f
#define EPSF   1e-5f

// Output layout
#define OFF_Q    0
#define OFF_LOSS 8388608
#define OFF_PERP 8388609
#define OFF_CB   8388610
#define OFF_CS   8650754
#define OFF_EDW  8651778

// Scratch
__device__ __align__(16) float g_dw[NUM_K * DIM];
__device__ float g_cnorm[NUM_K];
__device__ int   g_counts[NUM_K];
__device__ int   g_idx[NTOK];
__device__ float g_sumsq;
__device__ float g_csadj[NUM_K];
__device__ int   g_off[NUM_K];
__device__ int   g_cur[NUM_K];
__device__ int   g_toklist[NTOK];

// bf16 3-way splits (token-major / code-major, 256 cols each)
__device__ __align__(16) __nv_bfloat16 g_za[NTOK * DIM];
__device__ __align__(16) __nv_bfloat16 g_zb[NTOK * DIM];
__device__ __align__(16) __nv_bfloat16 g_zc[NTOK * DIM];
__device__ __align__(16) __nv_bfloat16 g_ca[NUM_K * DIM];
__device__ __align__(16) __nv_bfloat16 g_cb2[NUM_K * DIM];
__device__ __align__(16) __nv_bfloat16 g_cc[NUM_K * DIM];

__device__ __forceinline__ void split3(float x, __nv_bfloat16& a, __nv_bfloat16& b, __nv_bfloat16& c) {
    a = __float2bfloat16_rn(x);
    float r = x - __bfloat162float(a);
    b = __float2bfloat16_rn(r);
    float r2 = r - __bfloat162float(b);
    c = __float2bfloat16_rn(r2);
}
__device__ __forceinline__ uint32_t smem_u32(const void* p) {
    uint32_t a;
    asm("{ .reg .u64 t; cvta.to.shared.u64 t, %1; cvt.u32.u64 %0, t; }" : "=r"(a) : "l"(p));
    return a;
}
__device__ __forceinline__ void ldm_x4(uint32_t& r0, uint32_t& r1, uint32_t& r2, uint32_t& r3, uint32_t addr) {
    asm volatile("ldmatrix.sync.aligned.m8n8.x4.shared.b16 {%0,%1,%2,%3}, [%4];"
                 : "=r"(r0), "=r"(r1), "=r"(r2), "=r"(r3) : "r"(addr));
}
__device__ __forceinline__ void mma_bf16(float* c, const uint32_t* a, uint32_t b0, uint32_t b1) {
    asm volatile("mma.sync.aligned.m16n8k16.row.col.f32.bf16.bf16.f32 "
                 "{%0,%1,%2,%3}, {%4,%5,%6,%7}, {%8,%9}, {%0,%1,%2,%3};"
                 : "+f"(c[0]), "+f"(c[1]), "+f"(c[2]), "+f"(c[3])
                 : "r"(a[0]), "r"(a[1]), "r"(a[2]), "r"(a[3]), "r"(b0), "r"(b1));
}

// ---------------------------------------------------------------------------
// K1: codebook norms + codebook bf16 splits. grid=1024, block=64
// ---------------------------------------------------------------------------
__global__ void k_init(const float* __restrict__ cb) {
    const int k = blockIdx.x;
    const int t = threadIdx.x;
    const float4 c4 = ((const float4*)(cb + k * DIM))[t];
    float s = c4.x * c4.x + c4.y * c4.y + c4.z * c4.z + c4.w * c4.w;
    #pragma unroll
    for (int o = 16; o > 0; o >>= 1) s += __shfl_xor_sync(0xffffffffu, s, o);
    __shared__ float red[2];
    if ((t & 31) == 0) red[t >> 5] = s;
    #pragma unroll
    for (int j = 0; j < 4; j++) {
        const int d = t + 64 * j;
        __nv_bfloat16 a, b, c;
        split3(cb[k * DIM + d], a, b, c);
        g_ca [k * DIM + d] = a;
        g_cb2[k * DIM + d] = b;
        g_cc [k * DIM + d] = c;
    }
    __syncthreads();
    if (t == 0) {
        g_cnorm[k]  = red[0] + red[1];
        g_counts[k] = 0;
        if (k == 0) g_sumsq = 0.f;
    }
}

// ---------------------------------------------------------------------------
// K2: transpose + bf16-split z into token-major layout. grid=1024, block=256
// ---------------------------------------------------------------------------
__global__ __launch_bounds__(256)
void k_zsplit(const float* __restrict__ z) {
    __shared__ float s[256][33];
    const int b    = blockIdx.x >> 5;
    const int hwc  = blockIdx.x & 31;
    const int tid  = threadIdx.x;
    const int lane = tid & 31;
    const int grp  = tid >> 5;   // 0..7

    const float* zb = z + (size_t)b * DIM * HWSZ + hwc * 32;
    #pragma unroll 8
    for (int dd = 0; dd < 32; ++dd) {
        const int d = grp * 32 + dd;
        s[d][lane] = zb[(size_t)d * HWSZ + lane];
    }
    __syncthreads();

    #pragma unroll
    for (int tg = 0; tg < 4; ++tg) {
        const int tok = tg * 8 + grp;
        const size_t rowo = ((size_t)(b * HWSZ + hwc * 32 + tok)) * DIM;
        #pragma unroll
        for (int j = 0; j < 4; ++j) {
            const int d0 = (j * 32 + lane) * 2;
            const float x0 = s[d0][tok];
            const float x1 = s[d0 + 1][tok];
            __nv_bfloat16 a0, b0, c0, a1, b1, c1;
            split3(x0, a0, b0, c0);
            split3(x1, a1, b1, c1);
            *(__nv_bfloat162*)(g_za + rowo + d0) = __nv_bfloat162(a0, a1);
            *(__nv_bfloat162*)(g_zb + rowo + d0) = __nv_bfloat162(b0, b1);
            *(__nv_bfloat162*)(g_zc + rowo + d0) = __nv_bfloat162(c0, c1);
        }
    }
}

// ---------------------------------------------------------------------------
// K3: 6-term bf16 mma.sync distance GEMM + argmin.
// grid=256 CTAs (128 tokens), block=256 (8 warps: 2M x 4N), warp tile 64x64.
// CTA tile 128 x 256; ct loop 4 over code tiles; K-chunks of 16.
// smem: per stage A:3x(128x48B)=18KB, B:3x(256x48B)=36KB; double buffer.
// ---------------------------------------------------------------------------
#define A_VST   6144              // bytes per A variant (128*48)
#define B_VST   12288             // bytes per B variant (256*48)
#define B_BASE  18432             // A region = 3*6144
#define STAGE_B 55296             // 54 KB
#define SMIN_O  110592            // sminv float[4][128]
#define SMINI_O 112640            // smini int[4][128]
#define SMEM_TOTAL 114688

__global__ __launch_bounds__(256, 1)
void k_argmin_mma() {
    extern __shared__ char smem[];
    const uint32_t sb = smem_u32(smem);

    const int tid   = threadIdx.x;
    const int lane  = tid & 31;
    const int wid   = tid >> 5;
    const int warpM = wid & 1;      // 0..1 (64 rows each)
    const int warpN = wid >> 1;     // 0..3 (64 cols each)
    const int gid   = lane >> 2;    // 0..7
    const int tq    = lane & 3;     // 0..3
    const int tok0  = blockIdx.x * 128;

    const __nv_bfloat16* zsp[3] = {g_za, g_zb, g_zc};
    const __nv_bfloat16* csp[3] = {g_ca, g_cb2, g_cc};

    float acc[4][8][4];
    #pragma unroll
    for (int mt = 0; mt < 4; ++mt)
        #pragma unroll
        for (int nt = 0; nt < 8; ++nt)
            #pragma unroll
            for (int c = 0; c < 4; ++c) acc[mt][nt][c] = 0.f;

    float minv[4][2];
    int   mini[4][2];
    #pragma unroll
    for (int mt = 0; mt < 4; ++mt) {
        minv[mt][0] = minv[mt][1] = 3.4e38f;
        mini[mt][0] = mini[mt][1] = 0;
    }

    // ldmatrix base addresses (per warp)
    // A: row = base + (lane&15), 16B-col = lane>>4
    const int a_row  = (lane & 15);
    const int a_coff = ((lane >> 4) & 1) * 16;
    // B: row = base + ((lane&16)?8:0) + (lane&7), 16B-col = (lane&8)?1:0
    const int b_row  = ((lane & 16) >> 1) + (lane & 7);
    const int b_coff = ((lane >> 3) & 1) * 16;

    // staging indices (per thread)
    const int st_row  = tid >> 1;      // 0..127
    const int st_h    = tid & 1;       // 16B half of 32B row

    uint4 ra[3], rb[6];
    auto stage_ldg = [&](int cc) {
        const int ct = cc >> 4;
        const int kc = cc & 15;
        const int ko = kc * 16 + st_h * 8;
        #pragma unroll
        for (int v = 0; v < 3; ++v)
            ra[v] = *(const uint4*)(zsp[v] + ((size_t)(tok0 + st_row) << 8) + ko);
        #pragma unroll
        for (int v = 0; v < 3; ++v)
            #pragma unroll
            for (int j = 0; j < 2; ++j)
                rb[v * 2 + j] = *(const uint4*)(csp[v] + ((size_t)(ct * 256 + st_row + 128 * j) << 8) + ko);
    };
    auto stage_sts = [&](int buf) {
        char* base = smem + buf * STAGE_B;
        #pragma unroll
        for (int v = 0; v < 3; ++v)
            *(uint4*)(base + v * A_VST + st_row * 48 + st_h * 16) = ra[v];
        #pragma unroll
        for (int v = 0; v < 3; ++v)
            #pragma unroll
            for (int j = 0; j < 2; ++j)
                *(uint4*)(base + B_BASE + v * B_VST + (st_row + 128 * j) * 48 + st_h * 16) = rb[v * 2 + j];
    };

    stage_ldg(0);
    stage_sts(0);
    __syncthreads();

    const int NPART[3] = {3, 2, 1};   // av=0 pairs {ca,cb,cc}; av=1 {ca,cb}; av=2 {ca}

    for (int cc = 0; cc < 64; ++cc) {
        const int buf = cc & 1;
        if (cc + 1 < 64) stage_ldg(cc + 1);

        const uint32_t abase = sb + buf * STAGE_B;
        const uint32_t bbase = abase + B_BASE;

        #pragma unroll
        for (int av = 0; av < 3; ++av) {
            uint32_t afr[4][4];
            #pragma unroll
            for (int mt = 0; mt < 4; ++mt) {
                const uint32_t addr = abase + av * A_VST
                    + (warpM * 64 + mt * 16 + a_row) * 48 + a_coff;
                ldm_x4(afr[mt][0], afr[mt][1], afr[mt][2], afr[mt][3], addr);
            }
            for (int bv = 0; bv < NPART[av]; ++bv) {
                #pragma unroll
                for (int p = 0; p < 4; ++p) {
                    uint32_t b0, b1, b2, b3;
                    const uint32_t addr = bbase + bv * B_VST
                        + (warpN * 64 + p * 16 + b_row) * 48 + b_coff;
                    ldm_x4(b0, b1, b2, b3, addr);
                    #pragma unroll
                    for (int mt = 0; mt < 4; ++mt) mma_bf16(acc[mt][2 * p],     afr[mt], b0, b1);
                    #pragma unroll
                    for (int mt = 0; mt < 4; ++mt) mma_bf16(acc[mt][2 * p + 1], afr[mt], b2, b3);
                }
            }
        }

        if ((cc & 15) == 15) {
            // fold code tile ct into running argmin (ascending n, strict <)
            const int ct = cc >> 4;
            #pragma unroll
            for (int mt = 0; mt < 4; ++mt) {
                #pragma unroll
                for (int nt = 0; nt < 8; ++nt) {
                    const int n0 = ct * 256 + warpN * 64 + nt * 8 + 2 * tq;
                    const float cn0 = __ldg(&g_cnorm[n0]);
                    const float cn1 = __ldg(&g_cnorm[n0 + 1]);
                    const float s00 = fmaf(-2.f, acc[mt][nt][0], cn0);
                    const float s01 = fmaf(-2.f, acc[mt][nt][1], cn1);
                    const float s10 = fmaf(-2.f, acc[mt][nt][2], cn0);
                    const float s11 = fmaf(-2.f, acc[mt][nt][3], cn1);
                    if (s00 < minv[mt][0]) { minv[mt][0] = s00; mini[mt][0] = n0; }
                    if (s01 < minv[mt][0]) { minv[mt][0] = s01; mini[mt][0] = n0 + 1; }
                    if (s10 < minv[mt][1]) { minv[mt][1] = s10; mini[mt][1] = n0; }
                    if (s11 < minv[mt][1]) { minv[mt][1] = s11; mini[mt][1] = n0 + 1; }
                    acc[mt][nt][0] = acc[mt][nt][1] = acc[mt][nt][2] = acc[mt][nt][3] = 0.f;
                }
            }
        }
        __syncthreads();
        if (cc + 1 < 64) { stage_sts(buf ^ 1); __syncthreads(); }
    }

    // reduce across tq lanes (4) within warp
    float* sminv = (float*)(smem + SMIN_O);
    int*   smini = (int*)(smem + SMINI_O);
    #pragma unroll
    for (int mt = 0; mt < 4; ++mt) {
        #pragma unroll
        for (int h = 0; h < 2; ++h) {
            float v  = minv[mt][h];
            int   ix = mini[mt][h];
            #pragma unroll
            for (int off = 1; off <= 2; off <<= 1) {
                const float ov = __shfl_xor_sync(0xffffffffu, v, off);
                const int   oi = __shfl_xor_sync(0xffffffffu, ix, off);
                if (ov < v || (ov == v && oi < ix)) { v = ov; ix = oi; }
            }
            if (tq == 0) {
                const int row = warpM * 64 + mt * 16 + h * 8 + gid;
                sminv[warpN * 128 + row] = v;
                smini[warpN * 128 + row] = ix;
            }
        }
    }
    __syncthreads();

    // combine 4 warpN partial argmins
    if (tid < 128) {
        float v = sminv[tid];
        int   i = smini[tid];
        #pragma unroll
        for (int wn = 1; wn < 4; ++wn) {
            const float ov = sminv[wn * 128 + tid];
            const int   oi = smini[wn * 128 + tid];
            if (ov < v || (ov == v && oi < i)) { v = ov; i = oi; }
        }
        g_idx[tok0 + tid] = i;
        atomicAdd(&g_counts[i], 1);
    }
}

// ---------------------------------------------------------------------------
// K4: quantized output + loss partial (no dw atomics). grid=1024, block=256
// ---------------------------------------------------------------------------
__global__ __launch_bounds__(256)
void k_quant(const float* __restrict__ z, const float* __restrict__ cb,
             float* __restrict__ out) {
    const int tid  = threadIdx.x;
    const int lane = tid & 31;
    const int w    = tid >> 5;
    const int tok0 = blockIdx.x * 32;
    const int b    = tok0 >> 10;
    const int hw   = (tok0 & 1023) + lane;
    const int tok  = tok0 + lane;
    const int k    = g_idx[tok];

    const float* zrow = z  + (size_t)b * DIM * HWSZ + hw;
    float*       qrow = out + OFF_Q + (size_t)b * DIM * HWSZ + hw;
    const float* crow = cb + (size_t)k * DIM;

    float acc = 0.f;
    #pragma unroll 8
    for (int dd = 0; dd < 32; ++dd) {
        const int d = w + dd * 8;
        const float zv = zrow[(size_t)d * HWSZ];
        const float cv = __ldg(&crow[d]);
        qrow[(size_t)d * HWSZ] = zv + (cv - zv);
        const float df = zv - cv;
        acc = fmaf(df, df, acc);
    }
    #pragma unroll
    for (int o = 16; o > 0; o >>= 1) acc += __shfl_xor_sync(0xffffffffu, acc, o);
    if (lane == 0) atomicAdd(&g_sumsq, acc);
}

// ---------------------------------------------------------------------------
// K5: exclusive prefix scan of counts. 1 block, 1024 threads
// ---------------------------------------------------------------------------
__global__ void k_offsets() {
    __shared__ int sc[NUM_K];
    const int t = threadIdx.x;
    const int c = g_counts[t];
    sc[t] = c;
    __syncthreads();
    for (int off = 1; off < NUM_K; off <<= 1) {
        const int v = (t >= off) ? sc[t - off] : 0;
        __syncthreads();
        sc[t] += v;
        __syncthreads();
    }
    const int excl = sc[t] - c;
    g_off[t] = excl;
    g_cur[t] = excl;
}

// ---------------------------------------------------------------------------
// K6: bucket tokens by code. grid=128, block=256
// ---------------------------------------------------------------------------
__global__ void k_bucket() {
    const int tok = blockIdx.x * 256 + threadIdx.x;
    const int k = g_idx[tok];
    const int pos = atomicAdd(&g_cur[k], 1);
    g_toklist[pos] = tok;
}

// ---------------------------------------------------------------------------
// K7: dw gather: one CTA per code sums its bucket. grid=1024, block=256
// ---------------------------------------------------------------------------
__global__ __launch_bounds__(256)
void k_dwgather() {
    const int k = blockIdx.x;
    const int d = threadIdx.x;
    const int start = g_off[k];
    const int cnt   = g_counts[k];
    float acc = 0.f;
    for (int i = 0; i < cnt; ++i) {
        const int tok = g_toklist[start + i];
        const size_t o = ((size_t)tok << 8) + d;
        acc += __bfloat162float(g_za[o]) + __bfloat162float(g_zb[o]) + __bfloat162float(g_zc[o]);
    }
    g_dw[(size_t)k * DIM + d] = acc;
}

// ---------------------------------------------------------------------------
// K8: cluster-size EMA, n-sum, perplexity, loss. 1 block, 1024 threads
// ---------------------------------------------------------------------------
__global__ void k_finalize1(const float* __restrict__ ema_cs, float* __restrict__ out) {
    __shared__ float red[32];
    __shared__ float nsh;
    const int k = threadIdx.x;

    const float cnt = (float)g_counts[k];
    const float ncs = ema_cs[k] * DECAYF + OMD * cnt;
    out[OFF_CS + k] = ncs;

    float s = ncs;
    #pragma unroll
    for (int o = 16; o > 0; o >>= 1) s += __shfl_xor_sync(0xffffffffu, s, o);
    if ((k & 31) == 0) red[k >> 5] = s;
    __syncthreads();
    if (k < 32) {
        float t = red[k];
        #pragma unroll
        for (int o = 16; o > 0; o >>= 1) t += __shfl_xor_sync(0xffffffffu, t, o);
        if (k == 0) nsh = t;
    }
    __syncthreads();
    const float n = nsh;
    g_csadj[k] = (ncs + EPSF) / (n + NUM_K * EPSF) * n;

    const float p = cnt / (float)NTOK;
    float s2 = p * logf(p + 1e-10f);
    #pragma unroll
    for (int o = 16; o > 0; o >>= 1) s2 += __shfl_xor_sync(0xffffffffu, s2, o);
    if ((k & 31) == 0) red[k >> 5] = s2;
    __syncthreads();
    if (k == 0) {
        float t = 0.f;
        #pragma unroll
        for (int i = 0; i < 32; i++) t += red[i];
        out[OFF_PERP] = expf(-t);
        out[OFF_LOSS] = CCOST * g_sumsq / (float)(NTOK * DIM);
    }
}

// ---------------------------------------------------------------------------
// K9: ema_dw EMA + codebook division. grid=1024, block=256
// ---------------------------------------------------------------------------
__global__ void k_finalize2(const float* __restrict__ ema_dw, float* __restrict__ out) {
    const int k = blockIdx.x;
    const int d = threadIdx.x;
    const size_t o = (size_t)k * DIM + d;
    const float nd = ema_dw[o] * DECAYF + OMD * g_dw[o];
    out[OFF_EDW + o] = nd;
    out[OFF_CB  + o] = nd / g_csadj[k];
}

// ---------------------------------------------------------------------------
extern "C" void kernel_launch(void* const* d_in, const int* in_sizes, int n_in,
                              void* d_out, int out_size) {
    const float* z      = (const float*)d_in[0];
    const float* cb     = (const float*)d_in[1];
    const float* ema_cs = (const float*)d_in[2];
    const float* ema_dw = (const float*)d_in[3];
    float* out = (float*)d_out;

    static int smem_set = 0;
    if (!smem_set) {
        cudaFuncSetAttribute(k_argmin_mma, cudaFuncAttributeMaxDynamicSharedMemorySize, SMEM_TOTAL);
        smem_set = 1;
    }

    k_init<<<NUM_K, 64>>>(cb);
    k_zsplit<<<1024, 256>>>(z);
    k_argmin_mma<<<NTOK / 128, 256, SMEM_TOTAL>>>();
    k_offsets<<<1, 1024>>>();
    k_bucket<<<NTOK / 256, 256>>>();
    k_quant<<<NTOK / 32, 256>>>(z, cb, out);
    k_dwgather<<<NUM_K, 256>>>();
    k_finalize1<<<1, 1024>>>(ema_cs, out);
    k_finalize2<<<NUM_K, DIM>>>(ema_dw, out);
}

// round 6
// speedup vs baseline: 1.7786x; 1.4782x over previous
#include <cuda_runtime.h>
#include <cuda_fp16.h>
#include <math.h>
#include <stdint.h>

// Problem constants
#define NUM_K  1024
#define DIM    256
#define HWSZ   1024
#define NTOK   32768
#define DECAYF 0.99f
#define OMD    0.01f
#define CCOST  0.25f
#define EPSF   1e-5f

// Output layout
#define OFF_Q    0
#define OFF_LOSS 8388608
#define OFF_PERP 8388609
#define OFF_CB   8388610
#define OFF_CS   8650754
#define OFF_EDW  8651778

// Scratch
__device__ __align__(16) float g_dw[NUM_K * DIM];
__device__ float g_cnorm[NUM_K];
__device__ int   g_counts[NUM_K];
__device__ int   g_idx[NTOK];
__device__ float g_sumsq;
__device__ float g_csadj[NUM_K];
__device__ int   g_off[NUM_K];
__device__ int   g_cur[NUM_K];
__device__ int   g_toklist[NTOK];

// fp16 2-way splits (token-major / code-major, 256 cols, K contiguous)
__device__ __align__(16) __half g_zh[NTOK * DIM];
__device__ __align__(16) __half g_zl[NTOK * DIM];
__device__ __align__(16) __half g_ch[NUM_K * DIM];
__device__ __align__(16) __half g_cl[NUM_K * DIM];

__device__ __forceinline__ void split2(float x, __half& h, __half& l) {
    h = __float2half_rn(x);
    l = __float2half_rn(x - __half2float(h));
}
__device__ __forceinline__ uint32_t smem_u32(const void* p) {
    uint32_t a;
    asm("{ .reg .u64 t; cvta.to.shared.u64 t, %1; cvt.u32.u64 %0, t; }" : "=r"(a) : "l"(p));
    return a;
}
__device__ __forceinline__ void ldm_x4(uint32_t& r0, uint32_t& r1, uint32_t& r2, uint32_t& r3, uint32_t addr) {
    asm volatile("ldmatrix.sync.aligned.m8n8.x4.shared.b16 {%0,%1,%2,%3}, [%4];"
                 : "=r"(r0), "=r"(r1), "=r"(r2), "=r"(r3) : "r"(addr));
}
__device__ __forceinline__ void mma_f16(float* c, const uint32_t* a, uint32_t b0, uint32_t b1) {
    asm volatile("mma.sync.aligned.m16n8k16.row.col.f32.f16.f16.f32 "
                 "{%0,%1,%2,%3}, {%4,%5,%6,%7}, {%8,%9}, {%0,%1,%2,%3};"
                 : "+f"(c[0]), "+f"(c[1]), "+f"(c[2]), "+f"(c[3])
                 : "r"(a[0]), "r"(a[1]), "r"(a[2]), "r"(a[3]), "r"(b0), "r"(b1));
}
__device__ __forceinline__ void cp16(uint32_t dst, const void* src) {
    asm volatile("cp.async.cg.shared.global [%0], [%1], 16;" :: "r"(dst), "l"(src));
}
__device__ __forceinline__ void cp_commit() { asm volatile("cp.async.commit_group;" ::: "memory"); }
template<int N> __device__ __forceinline__ void cp_wait() {
    asm volatile("cp.async.wait_group %0;" :: "n"(N) : "memory");
}

// ---------------------------------------------------------------------------
// K1: codebook norms + fp16 codebook splits + counts clear. grid=1024, block=64
// ---------------------------------------------------------------------------
__global__ void k_init(const float* __restrict__ cb) {
    const int k = blockIdx.x;
    const int t = threadIdx.x;
    const float4 c4 = ((const float4*)(cb + k * DIM))[t];
    float s = c4.x * c4.x + c4.y * c4.y + c4.z * c4.z + c4.w * c4.w;
    #pragma unroll
    for (int o = 16; o > 0; o >>= 1) s += __shfl_xor_sync(0xffffffffu, s, o);
    __shared__ float red[2];
    if ((t & 31) == 0) red[t >> 5] = s;
    #pragma unroll
    for (int j = 0; j < 4; j++) {
        const int d = t + 64 * j;
        __half h, l;
        split2(cb[k * DIM + d], h, l);
        g_ch[k * DIM + d] = h;
        g_cl[k * DIM + d] = l;
    }
    __syncthreads();
    if (t == 0) {
        g_cnorm[k]  = red[0] + red[1];
        g_counts[k] = 0;
    }
}

// ---------------------------------------------------------------------------
// K2: transpose + fp16-split z into token-major layout. grid=1024, block=256
// ---------------------------------------------------------------------------
__global__ __launch_bounds__(256)
void k_zsplit(const float* __restrict__ z) {
    __shared__ float s[256][33];
    const int b    = blockIdx.x >> 5;
    const int hwc  = blockIdx.x & 31;
    const int tid  = threadIdx.x;
    const int lane = tid & 31;
    const int grp  = tid >> 5;   // 0..7

    const float* zb = z + (size_t)b * DIM * HWSZ + hwc * 32;
    #pragma unroll 8
    for (int dd = 0; dd < 32; ++dd) {
        const int d = grp * 32 + dd;
        s[d][lane] = zb[(size_t)d * HWSZ + lane];
    }
    __syncthreads();

    #pragma unroll
    for (int tg = 0; tg < 4; ++tg) {
        const int tok = tg * 8 + grp;
        const size_t rowo = ((size_t)(b * HWSZ + hwc * 32 + tok)) * DIM;
        #pragma unroll
        for (int j = 0; j < 4; ++j) {
            const int d0 = (j * 32 + lane) * 2;
            __half h0, l0, h1, l1;
            split2(s[d0][tok], h0, l0);
            split2(s[d0 + 1][tok], h1, l1);
            *(__half2*)(g_zh + rowo + d0) = __halves2half2(h0, h1);
            *(__half2*)(g_zl + rowo + d0) = __halves2half2(l0, l1);
        }
    }
}

// ---------------------------------------------------------------------------
// K3 (launch slot 3): tiny clear (also positions the big kernel at launch #4
// for the ncu capture window)
// ---------------------------------------------------------------------------
__global__ void k_clear() {
    if (threadIdx.x == 0) g_sumsq = 0.f;
}

// ---------------------------------------------------------------------------
// K4: 3-term fp16 mma.sync distance GEMM + argmin.
// grid=256 CTAs (128 tokens), block=256 (8 warps: 2M x 4N), warp tile 64x64.
// CTA tile 128 x 256 codes; 4 code tiles; K-chunks of 16; cp.async 3-stage.
// Terms: zh*ch + zh*cl + zl*ch  (dropped zl*cl ~ 2^-22 relative).
// smem/stage: A 2x(128x48B)=12KB, B 2x(256x48B)=24KB -> 36KB; 3 stages.
// ---------------------------------------------------------------------------
#define A_VST   6144
#define B_VST   12288
#define B_BASE  12288
#define STAGE_B 36864
#define SMIN_O  110592
#define SMINI_O 112640
#define SMEM_TOTAL 114688

__global__ __launch_bounds__(256, 1)
void k_argmin_mma() {
    extern __shared__ char smem[];
    const uint32_t sb = smem_u32(smem);

    const int tid   = threadIdx.x;
    const int lane  = tid & 31;
    const int wid   = tid >> 5;
    const int warpM = wid & 1;      // 0..1 (64 rows each)
    const int warpN = wid >> 1;     // 0..3 (64 cols each)
    const int gid   = lane >> 2;    // 0..7
    const int tq    = lane & 3;     // 0..3
    const int tok0  = blockIdx.x * 128;

    float acc[4][8][4];
    #pragma unroll
    for (int mt = 0; mt < 4; ++mt)
        #pragma unroll
        for (int nt = 0; nt < 8; ++nt)
            #pragma unroll
            for (int c = 0; c < 4; ++c) acc[mt][nt][c] = 0.f;

    float minv[4][2];
    int   mini[4][2];
    #pragma unroll
    for (int mt = 0; mt < 4; ++mt) {
        minv[mt][0] = minv[mt][1] = 3.4e38f;
        mini[mt][0] = mini[mt][1] = 0;
    }

    // ldmatrix lane mappings (validated in R5)
    const int a_row  = (lane & 15);
    const int a_coff = ((lane >> 4) & 1) * 16;
    const int b_row  = ((lane & 16) >> 1) + (lane & 7);
    const int b_coff = ((lane >> 3) & 1) * 16;

    // cp.async staging indices
    const int st_row = tid >> 1;     // 0..127
    const int st_h   = tid & 1;      // 16B half of 32B row payload

    auto stage_issue = [&](int cc, uint32_t sbase) {
        const int ct = cc >> 4;
        const int kc = cc & 15;
        const int ko = kc * 16 + st_h * 8;
        const uint32_t adst = sbase + st_row * 48 + st_h * 16;
        cp16(adst,         g_zh + (((size_t)(tok0 + st_row)) << 8) + ko);
        cp16(adst + A_VST, g_zl + (((size_t)(tok0 + st_row)) << 8) + ko);
        #pragma unroll
        for (int j = 0; j < 2; ++j) {
            const uint32_t bdst = sbase + B_BASE + (st_row + 128 * j) * 48 + st_h * 16;
            const size_t bsrc = (((size_t)(ct * 256 + st_row + 128 * j)) << 8) + ko;
            cp16(bdst,         g_ch + bsrc);
            cp16(bdst + B_VST, g_cl + bsrc);
        }
        cp_commit();
    };

    stage_issue(0, sb);
    stage_issue(1, sb + STAGE_B);

    int sidx = 0;   // stage holding chunk cc
    for (int cc = 0; cc < 64; ++cc) {
        if (cc < 63) cp_wait<1>(); else cp_wait<0>();
        __syncthreads();
        if (cc + 2 < 64) {
            int nidx = sidx + 2; if (nidx >= 3) nidx -= 3;
            stage_issue(cc + 2, sb + nidx * STAGE_B);
        }

        const uint32_t abase = sb + sidx * STAGE_B;
        const uint32_t bbase = abase + B_BASE;

        #pragma unroll
        for (int av = 0; av < 2; ++av) {
            uint32_t afr[4][4];
            #pragma unroll
            for (int mt = 0; mt < 4; ++mt) {
                const uint32_t addr = abase + av * A_VST
                    + (warpM * 64 + mt * 16 + a_row) * 48 + a_coff;
                ldm_x4(afr[mt][0], afr[mt][1], afr[mt][2], afr[mt][3], addr);
            }
            const int nbv = (av == 0) ? 2 : 1;
            for (int bv = 0; bv < nbv; ++bv) {
                #pragma unroll
                for (int p = 0; p < 4; ++p) {
                    uint32_t b0, b1, b2, b3;
                    const uint32_t addr = bbase + bv * B_VST
                        + (warpN * 64 + p * 16 + b_row) * 48 + b_coff;
                    ldm_x4(b0, b1, b2, b3, addr);
                    #pragma unroll
                    for (int mt = 0; mt < 4; ++mt) mma_f16(acc[mt][2 * p],     afr[mt], b0, b1);
                    #pragma unroll
                    for (int mt = 0; mt < 4; ++mt) mma_f16(acc[mt][2 * p + 1], afr[mt], b2, b3);
                }
            }
        }

        if ((cc & 15) == 15) {
            const int ct = cc >> 4;
            #pragma unroll
            for (int mt = 0; mt < 4; ++mt) {
                #pragma unroll
                for (int nt = 0; nt < 8; ++nt) {
                    const int n0 = ct * 256 + warpN * 64 + nt * 8 + 2 * tq;
                    const float cn0 = __ldg(&g_cnorm[n0]);
                    const float cn1 = __ldg(&g_cnorm[n0 + 1]);
                    const float s00 = fmaf(-2.f, acc[mt][nt][0], cn0);
                    const float s01 = fmaf(-2.f, acc[mt][nt][1], cn1);
                    const float s10 = fmaf(-2.f, acc[mt][nt][2], cn0);
                    const float s11 = fmaf(-2.f, acc[mt][nt][3], cn1);
                    if (s00 < minv[mt][0]) { minv[mt][0] = s00; mini[mt][0] = n0; }
                    if (s01 < minv[mt][0]) { minv[mt][0] = s01; mini[mt][0] = n0 + 1; }
                    if (s10 < minv[mt][1]) { minv[mt][1] = s10; mini[mt][1] = n0; }
                    if (s11 < minv[mt][1]) { minv[mt][1] = s11; mini[mt][1] = n0 + 1; }
                    acc[mt][nt][0] = acc[mt][nt][1] = acc[mt][nt][2] = acc[mt][nt][3] = 0.f;
                }
            }
        }
        if (++sidx >= 3) sidx -= 3;
    }

    // reduce across tq lanes within warp
    float* sminv = (float*)(smem + SMIN_O);
    int*   smini = (int*)(smem + SMINI_O);
    #pragma unroll
    for (int mt = 0; mt < 4; ++mt) {
        #pragma unroll
        for (int h = 0; h < 2; ++h) {
            float v  = minv[mt][h];
            int   ix = mini[mt][h];
            #pragma unroll
            for (int off = 1; off <= 2; off <<= 1) {
                const float ov = __shfl_xor_sync(0xffffffffu, v, off);
                const int   oi = __shfl_xor_sync(0xffffffffu, ix, off);
                if (ov < v || (ov == v && oi < ix)) { v = ov; ix = oi; }
            }
            if (tq == 0) {
                const int row = warpM * 64 + mt * 16 + h * 8 + gid;
                sminv[warpN * 128 + row] = v;
                smini[warpN * 128 + row] = ix;
            }
        }
    }
    __syncthreads();

    // combine 4 warpN partials
    if (tid < 128) {
        float v = sminv[tid];
        int   i = smini[tid];
        #pragma unroll
        for (int wn = 1; wn < 4; ++wn) {
            const float ov = sminv[wn * 128 + tid];
            const int   oi = smini[wn * 128 + tid];
            if (ov < v || (ov == v && oi < i)) { v = ov; i = oi; }
        }
        g_idx[tok0 + tid] = i;
        atomicAdd(&g_counts[i], 1);
    }
}

// ---------------------------------------------------------------------------
// K5: exclusive prefix scan of counts. 1 block, 1024 threads
// ---------------------------------------------------------------------------
__global__ void k_offsets() {
    __shared__ int sc[NUM_K];
    const int t = threadIdx.x;
    const int c = g_counts[t];
    sc[t] = c;
    __syncthreads();
    for (int off = 1; off < NUM_K; off <<= 1) {
        const int v = (t >= off) ? sc[t - off] : 0;
        __syncthreads();
        sc[t] += v;
        __syncthreads();
    }
    const int excl = sc[t] - c;
    g_off[t] = excl;
    g_cur[t] = excl;
}

// ---------------------------------------------------------------------------
// K6: bucket tokens by code. grid=128, block=256
// ---------------------------------------------------------------------------
__global__ void k_bucket() {
    const int tok = blockIdx.x * 256 + threadIdx.x;
    const int k = g_idx[tok];
    const int pos = atomicAdd(&g_cur[k], 1);
    g_toklist[pos] = tok;
}

// ---------------------------------------------------------------------------
// K7: quantized output + loss partial. grid=1024, block=256
// ---------------------------------------------------------------------------
__global__ __launch_bounds__(256)
void k_quant(const float* __restrict__ z, const float* __restrict__ cb,
             float* __restrict__ out) {
    const int tid  = threadIdx.x;
    const int lane = tid & 31;
    const int w    = tid >> 5;
    const int tok0 = blockIdx.x * 32;
    const int b    = tok0 >> 10;
    const int hw   = (tok0 & 1023) + lane;
    const int tok  = tok0 + lane;
    const int k    = g_idx[tok];

    const float* zrow = z  + (size_t)b * DIM * HWSZ + hw;
    float*       qrow = out + OFF_Q + (size_t)b * DIM * HWSZ + hw;
    const float* crow = cb + (size_t)k * DIM;

    float acc = 0.f;
    #pragma unroll 8
    for (int dd = 0; dd < 32; ++dd) {
        const int d = w + dd * 8;
        const float zv = zrow[(size_t)d * HWSZ];
        const float cv = __ldg(&crow[d]);
        qrow[(size_t)d * HWSZ] = zv + (cv - zv);
        const float df = zv - cv;
        acc = fmaf(df, df, acc);
    }
    #pragma unroll
    for (int o = 16; o > 0; o >>= 1) acc += __shfl_xor_sync(0xffffffffu, acc, o);
    if (lane == 0) atomicAdd(&g_sumsq, acc);
}

// ---------------------------------------------------------------------------
// K8: dw gather: one CTA per code sums its bucket. grid=1024, block=256
// ---------------------------------------------------------------------------
__global__ __launch_bounds__(256)
void k_dwgather() {
    const int k = blockIdx.x;
    const int d = threadIdx.x;
    const int start = g_off[k];
    const int cnt   = g_counts[k];
    float acc = 0.f;
    for (int i = 0; i < cnt; ++i) {
        const int tok = g_toklist[start + i];
        const size_t o = ((size_t)tok << 8) + d;
        acc += __half2float(g_zh[o]) + __half2float(g_zl[o]);
    }
    g_dw[(size_t)k * DIM + d] = acc;
}

// ---------------------------------------------------------------------------
// K9: cluster-size EMA, n-sum, perplexity, loss. 1 block, 1024 threads
// ---------------------------------------------------------------------------
__global__ void k_finalize1(const float* __restrict__ ema_cs, float* __restrict__ out) {
    __shared__ float red[32];
    __shared__ float nsh;
    const int k = threadIdx.x;

    const float cnt = (float)g_counts[k];
    const float ncs = ema_cs[k] * DECAYF + OMD * cnt;
    out[OFF_CS + k] = ncs;

    float s = ncs;
    #pragma unroll
    for (int o = 16; o > 0; o >>= 1) s += __shfl_xor_sync(0xffffffffu, s, o);
    if ((k & 31) == 0) red[k >> 5] = s;
    __syncthreads();
    if (k < 32) {
        float t = red[k];
        #pragma unroll
        for (int o = 16; o > 0; o >>= 1) t += __shfl_xor_sync(0xffffffffu, t, o);
        if (k == 0) nsh = t;
    }
    __syncthreads();
    const float n = nsh;
    g_csadj[k] = (ncs + EPSF) / (n + NUM_K * EPSF) * n;

    const float p = cnt / (float)NTOK;
    float s2 = p * logf(p + 1e-10f);
    #pragma unroll
    for (int o = 16; o > 0; o >>= 1) s2 += __shfl_xor_sync(0xffffffffu, s2, o);
    if ((k & 31) == 0) red[k >> 5] = s2;
    __syncthreads();
    if (k == 0) {
        float t = 0.f;
        #pragma unroll
        for (int i = 0; i < 32; i++) t += red[i];
        out[OFF_PERP] = expf(-t);
        out[OFF_LOSS] = CCOST * g_sumsq / (float)(NTOK * DIM);
    }
}

// ---------------------------------------------------------------------------
// K10: ema_dw EMA + codebook division. grid=1024, block=256
// ---------------------------------------------------------------------------
__global__ void k_finalize2(const float* __restrict__ ema_dw, float* __restrict__ out) {
    const int k = blockIdx.x;
    const int d = threadIdx.x;
    const size_t o = (size_t)k * DIM + d;
    const float nd = ema_dw[o] * DECAYF + OMD * g_dw[o];
    out[OFF_EDW + o] = nd;
    out[OFF_CB  + o] = nd / g_csadj[k];
}

// ---------------------------------------------------------------------------
extern "C" void kernel_launch(void* const* d_in, const int* in_sizes, int n_in,
                              void* d_out, int out_size) {
    const float* z      = (const float*)d_in[0];
    const float* cb     = (const float*)d_in[1];
    const float* ema_cs = (const float*)d_in[2];
    const float* ema_dw = (const float*)d_in[3];
    float* out = (float*)d_out;

    cudaFuncSetAttribute(k_argmin_mma, cudaFuncAttributeMaxDynamicSharedMemorySize, SMEM_TOTAL);

    k_init<<<NUM_K, 64>>>(cb);
    k_zsplit<<<1024, 256>>>(z);
    k_clear<<<1, 32>>>();
    k_argmin_mma<<<NTOK / 128, 256, SMEM_TOTAL>>>();
    k_offsets<<<1, 1024>>>();
    k_bucket<<<NTOK / 256, 256>>>();
    k_quant<<<NTOK / 32, 256>>>(z, cb, out);
    k_dwgather<<<NUM_K, 256>>>();
    k_finalize1<<<1, 1024>>>(ema_cs, out);
    k_finalize2<<<NUM_K, DIM>>>(ema_dw, out);
}

// round 7
// speedup vs baseline: 1.8794x; 1.0567x over previous
#include <cuda_runtime.h>
#include <cuda_fp16.h>
#include <math.h>
#include <stdint.h>

// Problem constants
#define NUM_K  1024
#define DIM    256
#define HWSZ   1024
#define NTOK   32768
#define DECAYF 0.99f
#define OMD    0.01f
#define CCOST  0.25f
#define EPSF   1e-5f

// Output layout
#define OFF_Q    0
#define OFF_LOSS 8388608
#define OFF_PERP 8388609
#define OFF_CB   8388610
#define OFF_CS   8650754
#define OFF_EDW  8651778

// Scratch
__device__ __align__(16) float g_dw[NUM_K * DIM];
__device__ float g_cnorm[NUM_K];
__device__ int   g_counts[NUM_K];
__device__ int   g_idx[NTOK];
__device__ float g_sumsq;
__device__ float g_csadj[NUM_K];
__device__ int   g_off[NUM_K];
__device__ int   g_cur[NUM_K];
__device__ int   g_toklist[NTOK];

// fp16 2-way splits (token-major / code-major, 256 cols, K contiguous)
__device__ __align__(16) __half g_zh[NTOK * DIM];
__device__ __align__(16) __half g_zl[NTOK * DIM];
__device__ __align__(16) __half g_ch[NUM_K * DIM];
__device__ __align__(16) __half g_cl[NUM_K * DIM];

__device__ __forceinline__ void split2(float x, __half& h, __half& l) {
    h = __float2half_rn(x);
    l = __float2half_rn(x - __half2float(h));
}
__device__ __forceinline__ uint32_t smem_u32(const void* p) {
    uint32_t a;
    asm("{ .reg .u64 t; cvta.to.shared.u64 t, %1; cvt.u32.u64 %0, t; }" : "=r"(a) : "l"(p));
    return a;
}
__device__ __forceinline__ void ldm_x4(uint32_t& r0, uint32_t& r1, uint32_t& r2, uint32_t& r3, uint32_t addr) {
    asm volatile("ldmatrix.sync.aligned.m8n8.x4.shared.b16 {%0,%1,%2,%3}, [%4];"
                 : "=r"(r0), "=r"(r1), "=r"(r2), "=r"(r3) : "r"(addr));
}
__device__ __forceinline__ void mma_f16(float* c, const uint32_t* a, uint32_t b0, uint32_t b1) {
    asm volatile("mma.sync.aligned.m16n8k16.row.col.f32.f16.f16.f32 "
                 "{%0,%1,%2,%3}, {%4,%5,%6,%7}, {%8,%9}, {%0,%1,%2,%3};"
                 : "+f"(c[0]), "+f"(c[1]), "+f"(c[2]), "+f"(c[3])
                 : "r"(a[0]), "r"(a[1]), "r"(a[2]), "r"(a[3]), "r"(b0), "r"(b1));
}
__device__ __forceinline__ void cp16(uint32_t dst, const void* src) {
    asm volatile("cp.async.cg.shared.global [%0], [%1], 16;" :: "r"(dst), "l"(src));
}
__device__ __forceinline__ void cp_commit() { asm volatile("cp.async.commit_group;" ::: "memory"); }
template<int N> __device__ __forceinline__ void cp_wait() {
    asm volatile("cp.async.wait_group %0;" :: "n"(N) : "memory");
}

// ---------------------------------------------------------------------------
// K1: codebook norms + fp16 codebook splits + counts clear. grid=1024, block=64
// ---------------------------------------------------------------------------
__global__ void k_init(const float* __restrict__ cb) {
    const int k = blockIdx.x;
    const int t = threadIdx.x;
    const float4 c4 = ((const float4*)(cb + k * DIM))[t];
    float s = c4.x * c4.x + c4.y * c4.y + c4.z * c4.z + c4.w * c4.w;
    #pragma unroll
    for (int o = 16; o > 0; o >>= 1) s += __shfl_xor_sync(0xffffffffu, s, o);
    __shared__ float red[2];
    if ((t & 31) == 0) red[t >> 5] = s;
    #pragma unroll
    for (int j = 0; j < 4; j++) {
        const int d = t + 64 * j;
        __half h, l;
        split2(cb[k * DIM + d], h, l);
        g_ch[k * DIM + d] = h;
        g_cl[k * DIM + d] = l;
    }
    __syncthreads();
    if (t == 0) {
        g_cnorm[k]  = red[0] + red[1];
        g_counts[k] = 0;
    }
}

// ---------------------------------------------------------------------------
// K2: transpose + fp16-split z into token-major layout. grid=1024, block=256
// ---------------------------------------------------------------------------
__global__ __launch_bounds__(256)
void k_zsplit(const float* __restrict__ z) {
    __shared__ float s[256][33];
    const int b    = blockIdx.x >> 5;
    const int hwc  = blockIdx.x & 31;
    const int tid  = threadIdx.x;
    const int lane = tid & 31;
    const int grp  = tid >> 5;   // 0..7

    const float* zb = z + (size_t)b * DIM * HWSZ + hwc * 32;
    #pragma unroll 8
    for (int dd = 0; dd < 32; ++dd) {
        const int d = grp * 32 + dd;
        s[d][lane] = zb[(size_t)d * HWSZ + lane];
    }
    __syncthreads();

    #pragma unroll
    for (int tg = 0; tg < 4; ++tg) {
        const int tok = tg * 8 + grp;
        const size_t rowo = ((size_t)(b * HWSZ + hwc * 32 + tok)) * DIM;
        #pragma unroll
        for (int j = 0; j < 4; ++j) {
            const int d0 = (j * 32 + lane) * 2;
            __half h0, l0, h1, l1;
            split2(s[d0][tok], h0, l0);
            split2(s[d0 + 1][tok], h1, l1);
            *(__half2*)(g_zh + rowo + d0) = __halves2half2(h0, h1);
            *(__half2*)(g_zl + rowo + d0) = __halves2half2(l0, l1);
        }
    }
}

// ---------------------------------------------------------------------------
// K3 (launch slot 3): tiny clear
// ---------------------------------------------------------------------------
__global__ void k_clear() {
    if (threadIdx.x == 0) g_sumsq = 0.f;
}

// ---------------------------------------------------------------------------
// K4: 3-term fp16 mma.sync distance GEMM + argmin.
// grid=256 CTAs (128 tokens), block=512 (16 warps: 4M x 4N), warp tile 32x64.
// CTA tile 128 x 256 codes; 4 code tiles; K-chunks of 16; cp.async 3-stage.
// Terms: zh*ch + zh*cl + zl*ch  (dropped zl*cl ~ 2^-22 relative).
// ---------------------------------------------------------------------------
#define A_VST   6144
#define B_VST   12288
#define B_BASE  12288
#define STAGE_B 36864
#define SMIN_O  110592
#define SMINI_O 112640
#define SMEM_TOTAL 114688

__global__ __launch_bounds__(512, 1)
void k_argmin_mma() {
    extern __shared__ char smem[];
    const uint32_t sb = smem_u32(smem);

    const int tid   = threadIdx.x;
    const int lane  = tid & 31;
    const int wid   = tid >> 5;
    const int warpM = wid & 3;      // 0..3 (32 rows each)
    const int warpN = wid >> 2;     // 0..3 (64 cols each)
    const int gid   = lane >> 2;    // 0..7
    const int tq    = lane & 3;     // 0..3
    const int tok0  = blockIdx.x * 128;

    float acc[2][8][4];
    #pragma unroll
    for (int mt = 0; mt < 2; ++mt)
        #pragma unroll
        for (int nt = 0; nt < 8; ++nt)
            #pragma unroll
            for (int c = 0; c < 4; ++c) acc[mt][nt][c] = 0.f;

    float minv[2][2];
    int   mini[2][2];
    #pragma unroll
    for (int mt = 0; mt < 2; ++mt) {
        minv[mt][0] = minv[mt][1] = 3.4e38f;
        mini[mt][0] = mini[mt][1] = 0;
    }

    // ldmatrix lane mappings (validated R5/R6)
    const int a_row  = (lane & 15);
    const int a_coff = ((lane >> 4) & 1) * 16;
    const int b_row  = ((lane & 16) >> 1) + (lane & 7);
    const int b_coff = ((lane >> 3) & 1) * 16;

    // cp.async staging: 512 threads. A slots: 2var*128row*2half = 512 (1/thread);
    // B slots: 2var*256row*2half = 1024 (2/thread).
    const int a_var = tid >> 8;
    const int a_srow = (tid >> 1) & 127;
    const int a_half = tid & 1;

    auto stage_issue = [&](int cc, uint32_t sbase) {
        const int ct = cc >> 4;
        const int kc = cc & 15;
        {
            const int ko = kc * 16 + a_half * 8;
            const __half* src = (a_var ? g_zl : g_zh) + (((size_t)(tok0 + a_srow)) << 8) + ko;
            cp16(sbase + a_var * A_VST + a_srow * 48 + a_half * 16, src);
        }
        #pragma unroll
        for (int j = 0; j < 2; ++j) {
            const int i = tid + j * 512;
            const int v = i >> 9;
            const int row = (i >> 1) & 255;
            const int half = i & 1;
            const int ko = kc * 16 + half * 8;
            const __half* src = (v ? g_cl : g_ch) + (((size_t)(ct * 256 + row)) << 8) + ko;
            cp16(sbase + B_BASE + v * B_VST + row * 48 + half * 16, src);
        }
        cp_commit();
    };

    stage_issue(0, sb);
    stage_issue(1, sb + STAGE_B);

    int sidx = 0;
    for (int cc = 0; cc < 64; ++cc) {
        if (cc < 63) cp_wait<1>(); else cp_wait<0>();
        __syncthreads();
        if (cc + 2 < 64) {
            int nidx = sidx + 2; if (nidx >= 3) nidx -= 3;
            stage_issue(cc + 2, sb + nidx * STAGE_B);
        }

        const uint32_t abase = sb + sidx * STAGE_B;
        const uint32_t bbase = abase + B_BASE;

        #pragma unroll
        for (int av = 0; av < 2; ++av) {
            uint32_t afr[2][4];
            #pragma unroll
            for (int mt = 0; mt < 2; ++mt) {
                const uint32_t addr = abase + av * A_VST
                    + (warpM * 32 + mt * 16 + a_row) * 48 + a_coff;
                ldm_x4(afr[mt][0], afr[mt][1], afr[mt][2], afr[mt][3], addr);
            }
            const int nbv = (av == 0) ? 2 : 1;
            for (int bv = 0; bv < nbv; ++bv) {
                #pragma unroll
                for (int p = 0; p < 4; ++p) {
                    uint32_t b0, b1, b2, b3;
                    const uint32_t addr = bbase + bv * B_VST
                        + (warpN * 64 + p * 16 + b_row) * 48 + b_coff;
                    ldm_x4(b0, b1, b2, b3, addr);
                    #pragma unroll
                    for (int mt = 0; mt < 2; ++mt) mma_f16(acc[mt][2 * p],     afr[mt], b0, b1);
                    #pragma unroll
                    for (int mt = 0; mt < 2; ++mt) mma_f16(acc[mt][2 * p + 1], afr[mt], b2, b3);
                }
            }
        }

        if ((cc & 15) == 15) {
            const int ct = cc >> 4;
            #pragma unroll
            for (int mt = 0; mt < 2; ++mt) {
                #pragma unroll
                for (int nt = 0; nt < 8; ++nt) {
                    const int n0 = ct * 256 + warpN * 64 + nt * 8 + 2 * tq;
                    const float cn0 = __ldg(&g_cnorm[n0]);
                    const float cn1 = __ldg(&g_cnorm[n0 + 1]);
                    const float s00 = fmaf(-2.f, acc[mt][nt][0], cn0);
                    const float s01 = fmaf(-2.f, acc[mt][nt][1], cn1);
                    const float s10 = fmaf(-2.f, acc[mt][nt][2], cn0);
                    const float s11 = fmaf(-2.f, acc[mt][nt][3], cn1);
                    if (s00 < minv[mt][0]) { minv[mt][0] = s00; mini[mt][0] = n0; }
                    if (s01 < minv[mt][0]) { minv[mt][0] = s01; mini[mt][0] = n0 + 1; }
                    if (s10 < minv[mt][1]) { minv[mt][1] = s10; mini[mt][1] = n0; }
                    if (s11 < minv[mt][1]) { minv[mt][1] = s11; mini[mt][1] = n0 + 1; }
                    acc[mt][nt][0] = acc[mt][nt][1] = acc[mt][nt][2] = acc[mt][nt][3] = 0.f;
                }
            }
        }
        if (++sidx >= 3) sidx -= 3;
    }

    // reduce across tq lanes within warp
    float* sminv = (float*)(smem + SMIN_O);
    int*   smini = (int*)(smem + SMINI_O);
    #pragma unroll
    for (int mt = 0; mt < 2; ++mt) {
        #pragma unroll
        for (int h = 0; h < 2; ++h) {
            float v  = minv[mt][h];
            int   ix = mini[mt][h];
            #pragma unroll
            for (int off = 1; off <= 2; off <<= 1) {
                const float ov = __shfl_xor_sync(0xffffffffu, v, off);
                const int   oi = __shfl_xor_sync(0xffffffffu, ix, off);
                if (ov < v || (ov == v && oi < ix)) { v = ov; ix = oi; }
            }
            if (tq == 0) {
                const int row = warpM * 32 + mt * 16 + h * 8 + gid;
                sminv[warpN * 128 + row] = v;
                smini[warpN * 128 + row] = ix;
            }
        }
    }
    __syncthreads();

    // combine 4 warpN partials
    if (tid < 128) {
        float v = sminv[tid];
        int   i = smini[tid];
        #pragma unroll
        for (int wn = 1; wn < 4; ++wn) {
            const float ov = sminv[wn * 128 + tid];
            const int   oi = smini[wn * 128 + tid];
            if (ov < v || (ov == v && oi < i)) { v = ov; i = oi; }
        }
        g_idx[tok0 + tid] = i;
        atomicAdd(&g_counts[i], 1);
    }
}

// ---------------------------------------------------------------------------
// K5: exclusive prefix scan of counts. 1 block, 1024 threads
// ---------------------------------------------------------------------------
__global__ void k_offsets() {
    __shared__ int sc[NUM_K];
    const int t = threadIdx.x;
    const int c = g_counts[t];
    sc[t] = c;
    __syncthreads();
    for (int off = 1; off < NUM_K; off <<= 1) {
        const int v = (t >= off) ? sc[t - off] : 0;
        __syncthreads();
        sc[t] += v;
        __syncthreads();
    }
    const int excl = sc[t] - c;
    g_off[t] = excl;
    g_cur[t] = excl;
}

// ---------------------------------------------------------------------------
// K6: bucket tokens by code. grid=128, block=256
// ---------------------------------------------------------------------------
__global__ void k_bucket() {
    const int tok = blockIdx.x * 256 + threadIdx.x;
    const int k = g_idx[tok];
    const int pos = atomicAdd(&g_cur[k], 1);
    g_toklist[pos] = tok;
}

// ---------------------------------------------------------------------------
// K7: quantized output + loss partial; codebook rows staged in smem.
// grid=1024 (32 tokens), block=256
// ---------------------------------------------------------------------------
__global__ __launch_bounds__(256)
void k_quant(const float* __restrict__ z, const float* __restrict__ cb,
             float* __restrict__ out) {
    __shared__ float cs[32][257];
    __shared__ int   skr[32];
    const int tid  = threadIdx.x;
    const int lane = tid & 31;
    const int w    = tid >> 5;
    const int tok0 = blockIdx.x * 32;
    const int b    = tok0 >> 10;
    const int hw   = (tok0 & 1023) + lane;

    if (tid < 32) skr[tid] = g_idx[tok0 + tid];
    __syncthreads();
    // coalesced load of the 32 selected code rows
    #pragma unroll
    for (int i = 0; i < 8; ++i) {
        const int slot = tid + i * 256;          // 0..2047
        const int row  = slot >> 6;              // 0..31
        const int q    = slot & 63;              // float4 index
        const float4 v = __ldg((const float4*)(cb + (size_t)skr[row] * DIM) + q);
        cs[row][q * 4 + 0] = v.x;
        cs[row][q * 4 + 1] = v.y;
        cs[row][q * 4 + 2] = v.z;
        cs[row][q * 4 + 3] = v.w;
    }
    __syncthreads();

    const float* zrow = z  + (size_t)b * DIM * HWSZ + hw;
    float*       qrow = out + OFF_Q + (size_t)b * DIM * HWSZ + hw;

    float acc = 0.f;
    #pragma unroll 8
    for (int dd = 0; dd < 32; ++dd) {
        const int d = w + dd * 8;
        const float zv = zrow[(size_t)d * HWSZ];
        const float cv = cs[lane][d];
        qrow[(size_t)d * HWSZ] = zv + (cv - zv);
        const float df = zv - cv;
        acc = fmaf(df, df, acc);
    }
    #pragma unroll
    for (int o = 16; o > 0; o >>= 1) acc += __shfl_xor_sync(0xffffffffu, acc, o);
    if (lane == 0) atomicAdd(&g_sumsq, acc);
}

// ---------------------------------------------------------------------------
// K8: dw gather: one CTA per code sums its bucket (unrolled for MLP).
// grid=1024, block=256
// ---------------------------------------------------------------------------
__global__ __launch_bounds__(256)
void k_dwgather() {
    const int k = blockIdx.x;
    const int d = threadIdx.x;
    const int start = g_off[k];
    const int cnt   = g_counts[k];
    float acc = 0.f;
    int i = 0;
    for (; i + 4 <= cnt; i += 4) {
        const int t0 = g_toklist[start + i];
        const int t1 = g_toklist[start + i + 1];
        const int t2 = g_toklist[start + i + 2];
        const int t3 = g_toklist[start + i + 3];
        const float v0 = __half2float(g_zh[((size_t)t0 << 8) + d]) + __half2float(g_zl[((size_t)t0 << 8) + d]);
        const float v1 = __half2float(g_zh[((size_t)t1 << 8) + d]) + __half2float(g_zl[((size_t)t1 << 8) + d]);
        const float v2 = __half2float(g_zh[((size_t)t2 << 8) + d]) + __half2float(g_zl[((size_t)t2 << 8) + d]);
        const float v3 = __half2float(g_zh[((size_t)t3 << 8) + d]) + __half2float(g_zl[((size_t)t3 << 8) + d]);
        acc += (v0 + v1) + (v2 + v3);
    }
    for (; i < cnt; ++i) {
        const int tok = g_toklist[start + i];
        const size_t o = ((size_t)tok << 8) + d;
        acc += __half2float(g_zh[o]) + __half2float(g_zl[o]);
    }
    g_dw[(size_t)k * DIM + d] = acc;
}

// ---------------------------------------------------------------------------
// K9: cluster-size EMA, n-sum, perplexity, loss. 1 block, 1024 threads
// ---------------------------------------------------------------------------
__global__ void k_finalize1(const float* __restrict__ ema_cs, float* __restrict__ out) {
    __shared__ float red[32];
    __shared__ float nsh;
    const int k = threadIdx.x;

    const float cnt = (float)g_counts[k];
    const float ncs = ema_cs[k] * DECAYF + OMD * cnt;
    out[OFF_CS + k] = ncs;

    float s = ncs;
    #pragma unroll
    for (int o = 16; o > 0; o >>= 1) s += __shfl_xor_sync(0xffffffffu, s, o);
    if ((k & 31) == 0) red[k >> 5] = s;
    __syncthreads();
    if (k < 32) {
        float t = red[k];
        #pragma unroll
        for (int o = 16; o > 0; o >>= 1) t += __shfl_xor_sync(0xffffffffu, t, o);
        if (k == 0) nsh = t;
    }
    __syncthreads();
    const float n = nsh;
    g_csadj[k] = (ncs + EPSF) / (n + NUM_K * EPSF) * n;

    const float p = cnt / (float)NTOK;
    float s2 = p * logf(p + 1e-10f);
    #pragma unroll
    for (int o = 16; o > 0; o >>= 1) s2 += __shfl_xor_sync(0xffffffffu, s2, o);
    if ((k & 31) == 0) red[k >> 5] = s2;
    __syncthreads();
    if (k == 0) {
        float t = 0.f;
        #pragma unroll
        for (int i = 0; i < 32; i++) t += red[i];
        out[OFF_PERP] = expf(-t);
        out[OFF_LOSS] = CCOST * g_sumsq / (float)(NTOK * DIM);
    }
}

// ---------------------------------------------------------------------------
// K10: ema_dw EMA + codebook division. grid=1024, block=256
// ---------------------------------------------------------------------------
__global__ void k_finalize2(const float* __restrict__ ema_dw, float* __restrict__ out) {
    const int k = blockIdx.x;
    const int d = threadIdx.x;
    const size_t o = (size_t)k * DIM + d;
    const float nd = ema_dw[o] * DECAYF + OMD * g_dw[o];
    out[OFF_EDW + o] = nd;
    out[OFF_CB  + o] = nd / g_csadj[k];
}

// ---------------------------------------------------------------------------
extern "C" void kernel_launch(void* const* d_in, const int* in_sizes, int n_in,
                              void* d_out, int out_size) {
    const float* z      = (const float*)d_in[0];
    const float* cb     = (const float*)d_in[1];
    const float* ema_cs = (const float*)d_in[2];
    const float* ema_dw = (const float*)d_in[3];
    float* out = (float*)d_out;

    cudaFuncSetAttribute(k_argmin_mma, cudaFuncAttributeMaxDynamicSharedMemorySize, SMEM_TOTAL);

    k_init<<<NUM_K, 64>>>(cb);
    k_zsplit<<<1024, 256>>>(z);
    k_clear<<<1, 32>>>();
    k_argmin_mma<<<NTOK / 128, 512, SMEM_TOTAL>>>();
    k_offsets<<<1, 1024>>>();
    k_bucket<<<NTOK / 256, 256>>>();
    k_quant<<<NTOK / 32, 256>>>(z, cb, out);
    k_dwgather<<<NUM_K, 256>>>();
    k_finalize1<<<1, 1024>>>(ema_cs, out);
    k_finalize2<<<NUM_K, DIM>>>(ema_dw, out);
}

// round 8
// speedup vs baseline: 2.3296x; 1.2396x over previous
#include <cuda_runtime.h>
#include <cuda_fp16.h>
#include <math.h>
#include <stdint.h>

// Problem constants
#define NUM_K  1024
#define DIM    256
#define HWSZ   1024
#define NTOK   32768
#define DECAYF 0.99f
#define OMD    0.01f
#define CCOST  0.25f
#define EPSF   1e-5f

// Output layout
#define OFF_Q    0
#define OFF_LOSS 8388608
#define OFF_PERP 8388609
#define OFF_CB   8388610
#define OFF_CS   8650754
#define OFF_EDW  8651778

// Scratch
__device__ __align__(16) float g_dw[NUM_K * DIM];
__device__ float g_cnorm[NUM_K];
__device__ int   g_counts[NUM_K];
__device__ int   g_idx[NTOK];
__device__ float g_sumz;      // sum over tokens of ||z||^2
__device__ float g_summin;    // sum over tokens of min score (= ||c||^2 - 2 z.c)
__device__ float g_csadj[NUM_K];
__device__ int   g_off[NUM_K];
__device__ int   g_cur[NUM_K];
__device__ int   g_toklist[NTOK];

// fp16 2-way splits (token-major / code-major, 256 cols, K contiguous)
__device__ __align__(16) __half g_zh[NTOK * DIM];
__device__ __align__(16) __half g_zl[NTOK * DIM];
__device__ __align__(16) __half g_ch[NUM_K * DIM];
__device__ __align__(16) __half g_cl[NUM_K * DIM];

__device__ __forceinline__ void split2(float x, __half& h, __half& l) {
    h = __float2half_rn(x);
    l = __float2half_rn(x - __half2float(h));
}
__device__ __forceinline__ uint32_t smem_u32(const void* p) {
    uint32_t a;
    asm("{ .reg .u64 t; cvta.to.shared.u64 t, %1; cvt.u32.u64 %0, t; }" : "=r"(a) : "l"(p));
    return a;
}
__device__ __forceinline__ void ldm_x4(uint32_t& r0, uint32_t& r1, uint32_t& r2, uint32_t& r3, uint32_t addr) {
    asm volatile("ldmatrix.sync.aligned.m8n8.x4.shared.b16 {%0,%1,%2,%3}, [%4];"
                 : "=r"(r0), "=r"(r1), "=r"(r2), "=r"(r3) : "r"(addr));
}
__device__ __forceinline__ void mma_f16(float* c, const uint32_t* a, uint32_t b0, uint32_t b1) {
    asm volatile("mma.sync.aligned.m16n8k16.row.col.f32.f16.f16.f32 "
                 "{%0,%1,%2,%3}, {%4,%5,%6,%7}, {%8,%9}, {%0,%1,%2,%3};"
                 : "+f"(c[0]), "+f"(c[1]), "+f"(c[2]), "+f"(c[3])
                 : "r"(a[0]), "r"(a[1]), "r"(a[2]), "r"(a[3]), "r"(b0), "r"(b1));
}
__device__ __forceinline__ void cp16(uint32_t dst, const void* src) {
    asm volatile("cp.async.cg.shared.global [%0], [%1], 16;" :: "r"(dst), "l"(src));
}
__device__ __forceinline__ void cp_commit() { asm volatile("cp.async.commit_group;" ::: "memory"); }
template<int N> __device__ __forceinline__ void cp_wait() {
    asm volatile("cp.async.wait_group %0;" :: "n"(N) : "memory");
}

// ---------------------------------------------------------------------------
// K1: codebook norms + fp16 codebook splits + clears. grid=1024, block=64
// ---------------------------------------------------------------------------
__global__ void k_init(const float* __restrict__ cb) {
    const int k = blockIdx.x;
    const int t = threadIdx.x;
    const float4 c4 = ((const float4*)(cb + k * DIM))[t];
    float s = c4.x * c4.x + c4.y * c4.y + c4.z * c4.z + c4.w * c4.w;
    #pragma unroll
    for (int o = 16; o > 0; o >>= 1) s += __shfl_xor_sync(0xffffffffu, s, o);
    __shared__ float red[2];
    if ((t & 31) == 0) red[t >> 5] = s;
    #pragma unroll
    for (int j = 0; j < 4; j++) {
        const int d = t + 64 * j;
        __half h, l;
        split2(cb[k * DIM + d], h, l);
        g_ch[k * DIM + d] = h;
        g_cl[k * DIM + d] = l;
    }
    __syncthreads();
    if (t == 0) {
        g_cnorm[k]  = red[0] + red[1];
        g_counts[k] = 0;
        if (k == 0) g_sumz = 0.f;
    }
}

// ---------------------------------------------------------------------------
// K2: transpose + fp16-split z + ||z||^2 sum. grid=1024, block=256
// ---------------------------------------------------------------------------
__global__ __launch_bounds__(256)
void k_zsplit(const float* __restrict__ z) {
    __shared__ float s[256][33];
    __shared__ float zred[8];
    const int b    = blockIdx.x >> 5;
    const int hwc  = blockIdx.x & 31;
    const int tid  = threadIdx.x;
    const int lane = tid & 31;
    const int grp  = tid >> 5;   // 0..7

    const float* zb = z + (size_t)b * DIM * HWSZ + hwc * 32;
    #pragma unroll 8
    for (int dd = 0; dd < 32; ++dd) {
        const int d = grp * 32 + dd;
        s[d][lane] = zb[(size_t)d * HWSZ + lane];
    }
    __syncthreads();

    float zacc = 0.f;
    #pragma unroll
    for (int tg = 0; tg < 4; ++tg) {
        const int tok = tg * 8 + grp;
        const size_t rowo = ((size_t)(b * HWSZ + hwc * 32 + tok)) * DIM;
        #pragma unroll
        for (int j = 0; j < 4; ++j) {
            const int d0 = (j * 32 + lane) * 2;
            const float x0 = s[d0][tok];
            const float x1 = s[d0 + 1][tok];
            zacc = fmaf(x0, x0, zacc);
            zacc = fmaf(x1, x1, zacc);
            __half h0, l0, h1, l1;
            split2(x0, h0, l0);
            split2(x1, h1, l1);
            *(__half2*)(g_zh + rowo + d0) = __halves2half2(h0, h1);
            *(__half2*)(g_zl + rowo + d0) = __halves2half2(l0, l1);
        }
    }
    #pragma unroll
    for (int o = 16; o > 0; o >>= 1) zacc += __shfl_xor_sync(0xffffffffu, zacc, o);
    if (lane == 0) zred[grp] = zacc;
    __syncthreads();
    if (tid == 0) {
        float t = 0.f;
        #pragma unroll
        for (int i = 0; i < 8; ++i) t += zred[i];
        atomicAdd(&g_sumz, t);
    }
}

// ---------------------------------------------------------------------------
// K3 (slot 3): clear minv accumulator
// ---------------------------------------------------------------------------
__global__ void k_clear() {
    if (threadIdx.x == 0) g_summin = 0.f;
}

// ---------------------------------------------------------------------------
// K4: 3-term fp16 mma.sync distance GEMM + argmin + loss partial.
// grid=256 CTAs (128 tokens), block=512 (16 warps: 4M x 4N), warp tile 32x64.
// K-chunks of 32 (stride-80B rows, ldmatrix conflict-free); 3-stage cp.async.
// ---------------------------------------------------------------------------
#define RSTR    80                   // row stride bytes (40 halves)
#define A_VST   (128 * RSTR)         // 10240
#define B_VST   (256 * RSTR)         // 20480
#define B_BASE  (2 * A_VST)          // 20480
#define STAGE_B (B_BASE + 2 * B_VST) // 61440
#define SMIN_O  (3 * STAGE_B)        // 184320
#define SMINI_O (SMIN_O + 2048)
#define SMEM_TOTAL (SMINI_O + 2048)  // 188416

__global__ __launch_bounds__(512, 1)
void k_argmin_mma() {
    extern __shared__ char smem[];
    const uint32_t sb = smem_u32(smem);

    const int tid   = threadIdx.x;
    const int lane  = tid & 31;
    const int wid   = tid >> 5;
    const int warpM = wid & 3;      // 0..3 (32 rows)
    const int warpN = wid >> 2;     // 0..3 (64 cols)
    const int gid   = lane >> 2;
    const int tq    = lane & 3;
    const int tok0  = blockIdx.x * 128;

    float acc[2][8][4];
    #pragma unroll
    for (int mt = 0; mt < 2; ++mt)
        #pragma unroll
        for (int nt = 0; nt < 8; ++nt)
            #pragma unroll
            for (int c = 0; c < 4; ++c) acc[mt][nt][c] = 0.f;

    float minv[2][2];
    int   mini[2][2];
    #pragma unroll
    for (int mt = 0; mt < 2; ++mt) {
        minv[mt][0] = minv[mt][1] = 3.4e38f;
        mini[mt][0] = mini[mt][1] = 0;
    }

    const int a_row  = (lane & 15);
    const int a_coff = ((lane >> 4) & 1) * 16;
    const int b_row  = ((lane & 16) >> 1) + (lane & 7);
    const int b_coff = ((lane >> 3) & 1) * 16;

    // staging: A 1024 slots (2/thread), B 2048 slots (4/thread); 16B each
    auto stage_issue = [&](int cc, uint32_t sbase) {
        const int ct = cc >> 3;
        const int kc = cc & 7;          // K-chunk of 32
        #pragma unroll
        for (int jj = 0; jj < 2; ++jj) {
            const int i = tid * 2 + jj;
            const int v = i >> 9;
            const int row = (i >> 2) & 127;
            const int q = i & 3;
            const __half* src = (v ? g_zl : g_zh) + (((size_t)(tok0 + row)) << 8) + kc * 32 + q * 8;
            cp16(sbase + v * A_VST + row * RSTR + q * 16, src);
        }
        #pragma unroll
        for (int jj = 0; jj < 4; ++jj) {
            const int i = tid + jj * 512;
            const int v = i >> 10;
            const int row = (i >> 2) & 255;
            const int q = i & 3;
            const __half* src = (v ? g_cl : g_ch) + (((size_t)(ct * 256 + row)) << 8) + kc * 32 + q * 8;
            cp16(sbase + B_BASE + v * B_VST + row * RSTR + q * 16, src);
        }
        cp_commit();
    };

    stage_issue(0, sb);
    stage_issue(1, sb + STAGE_B);

    int sidx = 0;
    for (int cc = 0; cc < 32; ++cc) {
        if (cc < 31) cp_wait<1>(); else cp_wait<0>();
        __syncthreads();
        if (cc + 2 < 32) {
            int nidx = sidx + 2; if (nidx >= 3) nidx -= 3;
            stage_issue(cc + 2, sb + nidx * STAGE_B);
        }

        const uint32_t abase = sb + sidx * STAGE_B;
        const uint32_t bbase = abase + B_BASE;

        #pragma unroll
        for (int av = 0; av < 2; ++av) {
            const int nbv = (av == 0) ? 2 : 1;
            #pragma unroll
            for (int kg = 0; kg < 2; ++kg) {
                uint32_t afr[2][4];
                #pragma unroll
                for (int mt = 0; mt < 2; ++mt) {
                    const uint32_t addr = abase + av * A_VST
                        + (warpM * 32 + mt * 16 + a_row) * RSTR + kg * 32 + a_coff;
                    ldm_x4(afr[mt][0], afr[mt][1], afr[mt][2], afr[mt][3], addr);
                }
                for (int bv = 0; bv < nbv; ++bv) {
                    #pragma unroll
                    for (int p = 0; p < 4; ++p) {
                        uint32_t b0, b1, b2, b3;
                        const uint32_t addr = bbase + bv * B_VST
                            + (warpN * 64 + p * 16 + b_row) * RSTR + kg * 32 + b_coff;
                        ldm_x4(b0, b1, b2, b3, addr);
                        #pragma unroll
                        for (int mt = 0; mt < 2; ++mt) mma_f16(acc[mt][2 * p],     afr[mt], b0, b1);
                        #pragma unroll
                        for (int mt = 0; mt < 2; ++mt) mma_f16(acc[mt][2 * p + 1], afr[mt], b2, b3);
                    }
                }
            }
        }

        if ((cc & 7) == 7) {
            const int ct = cc >> 3;
            #pragma unroll
            for (int mt = 0; mt < 2; ++mt) {
                #pragma unroll
                for (int nt = 0; nt < 8; ++nt) {
                    const int n0 = ct * 256 + warpN * 64 + nt * 8 + 2 * tq;
                    const float cn0 = __ldg(&g_cnorm[n0]);
                    const float cn1 = __ldg(&g_cnorm[n0 + 1]);
                    const float s00 = fmaf(-2.f, acc[mt][nt][0], cn0);
                    const float s01 = fmaf(-2.f, acc[mt][nt][1], cn1);
                    const float s10 = fmaf(-2.f, acc[mt][nt][2], cn0);
                    const float s11 = fmaf(-2.f, acc[mt][nt][3], cn1);
                    if (s00 < minv[mt][0]) { minv[mt][0] = s00; mini[mt][0] = n0; }
                    if (s01 < minv[mt][0]) { minv[mt][0] = s01; mini[mt][0] = n0 + 1; }
                    if (s10 < minv[mt][1]) { minv[mt][1] = s10; mini[mt][1] = n0; }
                    if (s11 < minv[mt][1]) { minv[mt][1] = s11; mini[mt][1] = n0 + 1; }
                    acc[mt][nt][0] = acc[mt][nt][1] = acc[mt][nt][2] = acc[mt][nt][3] = 0.f;
                }
            }
        }
        if (++sidx >= 3) sidx -= 3;
    }

    // reduce across tq lanes within warp
    float* sminv = (float*)(smem + SMIN_O);
    int*   smini = (int*)(smem + SMINI_O);
    #pragma unroll
    for (int mt = 0; mt < 2; ++mt) {
        #pragma unroll
        for (int h = 0; h < 2; ++h) {
            float v  = minv[mt][h];
            int   ix = mini[mt][h];
            #pragma unroll
            for (int off = 1; off <= 2; off <<= 1) {
                const float ov = __shfl_xor_sync(0xffffffffu, v, off);
                const int   oi = __shfl_xor_sync(0xffffffffu, ix, off);
                if (ov < v || (ov == v && oi < ix)) { v = ov; ix = oi; }
            }
            if (tq == 0) {
                const int row = warpM * 32 + mt * 16 + h * 8 + gid;
                sminv[warpN * 128 + row] = v;
                smini[warpN * 128 + row] = ix;
            }
        }
    }
    __syncthreads();

    // combine 4 warpN partials; write idx, counts, and loss partial
    if (tid < 128) {
        float v = sminv[tid];
        int   i = smini[tid];
        #pragma unroll
        for (int wn = 1; wn < 4; ++wn) {
            const float ov = sminv[wn * 128 + tid];
            const int   oi = smini[wn * 128 + tid];
            if (ov < v || (ov == v && oi < i)) { v = ov; i = oi; }
        }
        g_idx[tok0 + tid] = i;
        atomicAdd(&g_counts[i], 1);
        // sum of min scores for the loss
        float sum = v;
        #pragma unroll
        for (int o = 16; o > 0; o >>= 1) sum += __shfl_xor_sync(0xffffffffu, sum, o);
        if (lane == 0) atomicAdd(&g_summin, sum);
    }
}

// ---------------------------------------------------------------------------
// K5: exclusive prefix scan of counts. 1 block, 1024 threads
// ---------------------------------------------------------------------------
__global__ void k_offsets() {
    __shared__ int sc[NUM_K];
    const int t = threadIdx.x;
    const int c = g_counts[t];
    sc[t] = c;
    __syncthreads();
    for (int off = 1; off < NUM_K; off <<= 1) {
        const int v = (t >= off) ? sc[t - off] : 0;
        __syncthreads();
        sc[t] += v;
        __syncthreads();
    }
    const int excl = sc[t] - c;
    g_off[t] = excl;
    g_cur[t] = excl;
}

// ---------------------------------------------------------------------------
// K6: bucket tokens by code. grid=128, block=256
// ---------------------------------------------------------------------------
__global__ void k_bucket() {
    const int tok = blockIdx.x * 256 + threadIdx.x;
    const int k = g_idx[tok];
    const int pos = atomicAdd(&g_cur[k], 1);
    g_toklist[pos] = tok;
}

// ---------------------------------------------------------------------------
// K7: quantized output = codebook gather (straight-through == codebook row).
// grid=1024 (32 tokens), block=256
// ---------------------------------------------------------------------------
__global__ __launch_bounds__(256)
void k_qgather(const float* __restrict__ cb, float* __restrict__ out) {
    __shared__ float cs[32][257];
    __shared__ int   skr[32];
    const int tid  = threadIdx.x;
    const int lane = tid & 31;
    const int w    = tid >> 5;
    const int tok0 = blockIdx.x * 32;
    const int b    = tok0 >> 10;
    const int hw   = (tok0 & 1023) + lane;

    if (tid < 32) skr[tid] = g_idx[tok0 + tid];
    __syncthreads();
    #pragma unroll
    for (int i = 0; i < 8; ++i) {
        const int slot = tid + i * 256;
        const int row  = slot >> 6;
        const int q    = slot & 63;
        const float4 v = __ldg((const float4*)(cb + (size_t)skr[row] * DIM) + q);
        cs[row][q * 4 + 0] = v.x;
        cs[row][q * 4 + 1] = v.y;
        cs[row][q * 4 + 2] = v.z;
        cs[row][q * 4 + 3] = v.w;
    }
    __syncthreads();

    float* qrow = out + OFF_Q + (size_t)b * DIM * HWSZ + hw;
    #pragma unroll 8
    for (int dd = 0; dd < 32; ++dd) {
        const int d = w + dd * 8;
        qrow[(size_t)d * HWSZ] = cs[lane][d];
    }
}

// ---------------------------------------------------------------------------
// K8: dw gather: one CTA per code sums its bucket. grid=1024, block=256
// ---------------------------------------------------------------------------
__global__ __launch_bounds__(256)
void k_dwgather() {
    const int k = blockIdx.x;
    const int d = threadIdx.x;
    const int start = g_off[k];
    const int cnt   = g_counts[k];
    float acc = 0.f;
    int i = 0;
    for (; i + 4 <= cnt; i += 4) {
        const int t0 = g_toklist[start + i];
        const int t1 = g_toklist[start + i + 1];
        const int t2 = g_toklist[start + i + 2];
        const int t3 = g_toklist[start + i + 3];
        const float v0 = __half2float(g_zh[((size_t)t0 << 8) + d]) + __half2float(g_zl[((size_t)t0 << 8) + d]);
        const float v1 = __half2float(g_zh[((size_t)t1 << 8) + d]) + __half2float(g_zl[((size_t)t1 << 8) + d]);
        const float v2 = __half2float(g_zh[((size_t)t2 << 8) + d]) + __half2float(g_zl[((size_t)t2 << 8) + d]);
        const float v3 = __half2float(g_zh[((size_t)t3 << 8) + d]) + __half2float(g_zl[((size_t)t3 << 8) + d]);
        acc += (v0 + v1) + (v2 + v3);
    }
    for (; i < cnt; ++i) {
        const int tok = g_toklist[start + i];
        const size_t o = ((size_t)tok << 8) + d;
        acc += __half2float(g_zh[o]) + __half2float(g_zl[o]);
    }
    g_dw[(size_t)k * DIM + d] = acc;
}

// ---------------------------------------------------------------------------
// K9: cluster-size EMA, n-sum, perplexity, loss. 1 block, 1024 threads
// ---------------------------------------------------------------------------
__global__ void k_finalize1(const float* __restrict__ ema_cs, float* __restrict__ out) {
    __shared__ float red[32];
    __shared__ float nsh;
    const int k = threadIdx.x;

    const float cnt = (float)g_counts[k];
    const float ncs = ema_cs[k] * DECAYF + OMD * cnt;
    out[OFF_CS + k] = ncs;

    float s = ncs;
    #pragma unroll
    for (int o = 16; o > 0; o >>= 1) s += __shfl_xor_sync(0xffffffffu, s, o);
    if ((k & 31) == 0) red[k >> 5] = s;
    __syncthreads();
    if (k < 32) {
        float t = red[k];
        #pragma unroll
        for (int o = 16; o > 0; o >>= 1) t += __shfl_xor_sync(0xffffffffu, t, o);
        if (k == 0) nsh = t;
    }
    __syncthreads();
    const float n = nsh;
    g_csadj[k] = (ncs + EPSF) / (n + NUM_K * EPSF) * n;

    const float p = cnt / (float)NTOK;
    float s2 = p * logf(p + 1e-10f);
    #pragma unroll
    for (int o = 16; o > 0; o >>= 1) s2 += __shfl_xor_sync(0xffffffffu, s2, o);
    if ((k & 31) == 0) red[k >> 5] = s2;
    __syncthreads();
    if (k == 0) {
        float t = 0.f;
        #pragma unroll
        for (int i = 0; i < 32; i++) t += red[i];
        out[OFF_PERP] = expf(-t);
        // commitment loss: mean ||z - c||^2 = (sum_min_scores + sum ||z||^2) / (N*D)
        out[OFF_LOSS] = CCOST * (g_summin + g_sumz) / (float)(NTOK * DIM);
    }
}

// ---------------------------------------------------------------------------
// K10: ema_dw EMA + codebook division. grid=1024, block=256
// ---------------------------------------------------------------------------
__global__ void k_finalize2(const float* __restrict__ ema_dw, float* __restrict__ out) {
    const int k = blockIdx.x;
    const int d = threadIdx.x;
    const size_t o = (size_t)k * DIM + d;
    const float nd = ema_dw[o] * DECAYF + OMD * g_dw[o];
    out[OFF_EDW + o] = nd;
    out[OFF_CB  + o] = nd / g_csadj[k];
}

// ---------------------------------------------------------------------------
extern "C" void kernel_launch(void* const* d_in, const int* in_sizes, int n_in,
                              void* d_out, int out_size) {
    const float* z      = (const float*)d_in[0];
    const float* cb     = (const float*)d_in[1];
    const float* ema_cs = (const float*)d_in[2];
    const float* ema_dw = (const float*)d_in[3];
    float* out = (float*)d_out;

    cudaFuncSetAttribute(k_argmin_mma, cudaFuncAttributeMaxDynamicSharedMemorySize, SMEM_TOTAL);

    k_init<<<NUM_K, 64>>>(cb);
    k_zsplit<<<1024, 256>>>(z);
    k_clear<<<1, 32>>>();
    k_argmin_mma<<<NTOK / 128, 512, SMEM_TOTAL>>>();
    k_offsets<<<1, 1024>>>();
    k_bucket<<<NTOK / 256, 256>>>();
    k_qgather<<<NTOK / 32, 256>>>(cb, out);
    k_dwgather<<<NUM_K, 256>>>();
    k_finalize1<<<1, 1024>>>(ema_cs, out);
    k_finalize2<<<NUM_K, DIM>>>(ema_dw, out);
}